// round 1
// baseline (speedup 1.0000x reference)
#include <cuda_runtime.h>
#include <cuda_bf16.h>

// Problem dims
#define BB 8
#define TT 20
#define MM 512
#define FF 16
#define HH 128
#define G3 384
#define BM 4096   // B*M
#define HALF 64
#define KK 10

// ---------------- scratch (device globals; no allocation allowed) ----------
__device__ __align__(128) float g_hid[BM * HH];          // last GRU hidden
__device__ __align__(128) float g_p1[BM * HALF];
__device__ __align__(128) float g_p2[BM * HALF];
__device__ __align__(128) float g_amx[BB * MM * MM];     // attention adjacency
__device__ __align__(128) float g_nrm[BM];
__device__ __align__(128) float g_A[BB * MM * MM];       // gated adjacency
__device__ __align__(128) float g_rl[BM * 30];           // conv features
__device__ __align__(128) float g_Z[BM * HH];            // r_l @ gc1_W
__device__ __align__(128) float g_h1[BM * HH];
__device__ __align__(128) float g_Z2[BM * KK];
__device__ __align__(128) float g_sp[BM * KK];           // out_spatial
__device__ __align__(128) float g_y[BM];

// ---------------- helpers ----------------
__device__ __forceinline__ float fsig(float x) {
    return __fdividef(1.f, 1.f + __expf(-x));
}
__device__ __forceinline__ float ftanh(float x) {
    x = fminf(15.f, fmaxf(-15.f, x));
    float t = __expf(2.f * x);
    return __fdividef(t - 1.f, t + 1.f);
}

// ============================================================================
// Kernel 1: GRU. 256 CTAs x 256 thr. 16 seqs/CTA, 2 seqs/warp.
// WhhT (128x384, padded stride 385) + WihT in smem; h in smem per seq.
// Lane owns gates g = lane+32j (j=0..3 -> r, 4..7 -> z, 8..11 -> n).
// ============================================================================
#define WTS 385
__global__ void __launch_bounds__(256, 1) gru_kernel(
    const float* __restrict__ X, const float* __restrict__ Wih,
    const float* __restrict__ Whh, const float* __restrict__ bih,
    const float* __restrict__ bhh)
{
    extern __shared__ float sm[];
    float* whhT = sm;                   // 128*385
    float* wihT = whhT + 128 * WTS;     // 16*385
    float* hbuf = wihT + 16 * WTS;      // 16*128
    float* xbuf = hbuf + 16 * 128;      // 256

    const int tid = threadIdx.x;
    const int lane = tid & 31;
    const int warp = tid >> 5;
    const int n0 = blockIdx.x * 16;
    const int b = n0 >> 9;
    const int m0 = n0 & 511;

    for (int idx = tid; idx < G3 * HH; idx += 256) {
        int g = idx >> 7, k = idx & 127;
        whhT[k * WTS + g] = Whh[idx];
    }
    for (int idx = tid; idx < G3 * FF; idx += 256) {
        int g = idx >> 4, f = idx & 15;
        wihT[f * WTS + g] = Wih[idx];
    }
    for (int idx = tid; idx < 16 * HH; idx += 256) hbuf[idx] = 0.f;

    float cr[4], cz[4], cnx[4], cnh[4];
#pragma unroll
    for (int j = 0; j < 4; j++) {
        int g = lane + 32 * j;
        cr[j]  = __ldg(bih + g)       + __ldg(bhh + g);
        cz[j]  = __ldg(bih + 128 + g) + __ldg(bhh + 128 + g);
        cnx[j] = __ldg(bih + 256 + g);
        cnh[j] = __ldg(bhh + 256 + g);
    }

    const int s0 = warp * 2, s1 = s0 + 1;
    float* h0p = hbuf + s0 * 128;
    float* h1p = hbuf + s1 * 128;

    for (int t = 0; t < TT; t++) {
        __syncthreads();
        xbuf[tid] = X[((b * TT + t) * MM + m0) * FF + tid];
        __syncthreads();

        float ar0[4], ar1[4], az0[4], az1[4], anx0[4], anx1[4], anh0[4], anh1[4];
#pragma unroll
        for (int j = 0; j < 4; j++) {
            ar0[j] = cr[j];  ar1[j] = cr[j];
            az0[j] = cz[j];  az1[j] = cz[j];
            anx0[j] = cnx[j]; anx1[j] = cnx[j];
            anh0[j] = cnh[j]; anh1[j] = cnh[j];
        }

        const float* xb0 = xbuf + s0 * 16;
        const float* xb1 = xbuf + s1 * 16;
#pragma unroll 4
        for (int f = 0; f < 16; f++) {
            float x0 = xb0[f], x1 = xb1[f];
            const float* wr = wihT + f * WTS + lane;
#pragma unroll
            for (int j = 0; j < 4; j++) {
                float w_r = wr[32 * j], w_z = wr[128 + 32 * j], w_n = wr[256 + 32 * j];
                ar0[j]  += x0 * w_r;  ar1[j]  += x1 * w_r;
                az0[j]  += x0 * w_z;  az1[j]  += x1 * w_z;
                anx0[j] += x0 * w_n;  anx1[j] += x1 * w_n;
            }
        }
#pragma unroll 2
        for (int k = 0; k < 128; k++) {
            float hk0 = h0p[k], hk1 = h1p[k];
            const float* wr = whhT + k * WTS + lane;
#pragma unroll
            for (int j = 0; j < 4; j++) {
                float w_r = wr[32 * j], w_z = wr[128 + 32 * j], w_n = wr[256 + 32 * j];
                ar0[j]  += hk0 * w_r;  ar1[j]  += hk1 * w_r;
                az0[j]  += hk0 * w_z;  az1[j]  += hk1 * w_z;
                anh0[j] += hk0 * w_n;  anh1[j] += hk1 * w_n;
            }
        }
        float hn0[4], hn1[4];
#pragma unroll
        for (int j = 0; j < 4; j++) {
            int idx = lane + 32 * j;
            float r0 = fsig(ar0[j]), z0 = fsig(az0[j]);
            float nn0 = ftanh(anx0[j] + r0 * anh0[j]);
            hn0[j] = (1.f - z0) * nn0 + z0 * h0p[idx];
            float r1 = fsig(ar1[j]), z1 = fsig(az1[j]);
            float nn1 = ftanh(anx1[j] + r1 * anh1[j]);
            hn1[j] = (1.f - z1) * nn1 + z1 * h1p[idx];
        }
        __syncwarp();
#pragma unroll
        for (int j = 0; j < 4; j++) {
            int idx = lane + 32 * j;
            h0p[idx] = hn0[j];
            h1p[idx] = hn1[j];
        }
    }
    __syncthreads();
#pragma unroll
    for (int j = 0; j < 4; j++) {
        int idx = lane + 32 * j;
        g_hid[(n0 + s0) * HH + idx] = h0p[idx];
        g_hid[(n0 + s1) * HH + idx] = h1p[idx];
    }
}

// ============================================================================
// Kernel 2: p1 = hid @ W1^T, p2 = hid @ W2^T   (BMx128)@(128x64) each
// 1024 blocks x 256 thr, 4 nodes/block, W1T/W2T (padded 65) in smem.
// ============================================================================
__global__ void __launch_bounds__(256) p1p2_kernel(
    const float* __restrict__ W1, const float* __restrict__ W2)
{
    extern __shared__ float sm[];
    float* w1t = sm;                // 128*65
    float* w2t = w1t + 128 * 65;    // 128*65
    float* hs  = w2t + 128 * 65;    // 4*128
    int tid = threadIdx.x;
    int n0 = blockIdx.x * 4;
    for (int idx = tid; idx < HALF * HH; idx += 256) {
        int k = idx >> 7, h = idx & 127;
        w1t[h * 65 + k] = W1[idx];
        w2t[h * 65 + k] = W2[idx];
    }
    for (int idx = tid; idx < 4 * HH; idx += 256) hs[idx] = g_hid[n0 * HH + idx];
    __syncthreads();
    int s = tid >> 6, kk = tid & 63;
    const float* hr = hs + s * 128;
    float a1 = 0.f, a2 = 0.f;
#pragma unroll 4
    for (int h = 0; h < 128; h++) {
        float hv = hr[h];
        a1 += hv * w1t[h * 65 + kk];
        a2 += hv * w2t[h * 65 + kk];
    }
    g_p1[(n0 + s) * HALF + kk] = a1;
    g_p2[(n0 + s) * HALF + kk] = a2;
}

// ============================================================================
// Kernel 3: a_mx[b,i,j] = sum_k elu(p1[b,j,k]+p2[b,i,k]+b1[k]) * V[k] + bv
// grid (32 jt, 32 it, 8 b), 16x16 tile per block.
// ============================================================================
__global__ void __launch_bounds__(256) amx_kernel(
    const float* __restrict__ b1, const float* __restrict__ V,
    const float* __restrict__ bv)
{
    __shared__ float p1t[16 * 65], p2t[16 * 65], b1s[64], Vs[64];
    int b = blockIdx.z, i0 = blockIdx.y * 16, j0 = blockIdx.x * 16;
    int tid = threadIdx.x;
    for (int idx = tid; idx < 16 * 64; idx += 256) {
        int r = idx >> 6, k = idx & 63;
        p1t[r * 65 + k] = g_p1[(b * MM + j0 + r) * HALF + k];
        p2t[r * 65 + k] = g_p2[(b * MM + i0 + r) * HALF + k];
    }
    if (tid < 64) { b1s[tid] = b1[tid]; Vs[tid] = V[tid]; }
    __syncthreads();
    int ii = tid >> 4, jj = tid & 15;
    const float* P1 = p1t + jj * 65;
    const float* P2 = p2t + ii * 65;
    float acc = 0.f;
#pragma unroll 4
    for (int k = 0; k < 64; k++) {
        float v = P1[k] + P2[k] + b1s[k];
        float e = v > 0.f ? v : (__expf(v) - 1.f);
        acc += e * Vs[k];
    }
    g_amx[(b * MM + i0 + ii) * MM + j0 + jj] = acc + bv[0];
}

// Kernel 3b: column L2 norms over axis i
__global__ void colnorm_kernel()
{
    int b = blockIdx.y;
    int j = blockIdx.x * 256 + threadIdx.x;
    const float* base = g_amx + b * MM * MM + j;
    float s = 0.f;
#pragma unroll 8
    for (int i = 0; i < MM; i++) { float v = base[i * MM]; s += v * v; }
    g_nrm[b * MM + j] = sqrtf(s);
}

// Kernel 3c: in-place normalize
__global__ void normdiv_kernel()
{
    int idx = blockIdx.x * 512 + threadIdx.x;   // 2^21 total
    int b = idx >> 18;
    int j = idx & 511;
    g_amx[idx] = g_amx[idx] / fmaxf(g_nrm[b * MM + j], 1e-12f);
}

// ============================================================================
// Kernel 4: per-node conv1d branch -> r_l (BM x 30) with relu
// 256 blocks x 160 thr (16 nodes x 10 channels)
// ============================================================================
__global__ void __launch_bounds__(160) conv_kernel(
    const float* __restrict__ X, const float* __restrict__ cw,
    const float* __restrict__ cb, const float* __restrict__ clw,
    const float* __restrict__ clb)
{
    __shared__ float xs[16 * 320];   // [s][w*16+f]
    __shared__ float cws[3200];      // (10,16,20)
    __shared__ float clws[1600];     // (10,16,10)
    int tid = threadIdx.x;
    int n0 = blockIdx.x * 16;
    int b = n0 >> 9, m0 = n0 & 511;
    for (int idx = tid; idx < 3200; idx += 160) cws[idx] = cw[idx];
    for (int idx = tid; idx < 1600; idx += 160) clws[idx] = clw[idx];
    for (int idx = tid; idx < 5120; idx += 160) {
        int w = idx >> 8, rem = idx & 255;
        int s = rem >> 4, f = rem & 15;
        xs[s * 320 + w * 16 + f] = X[((b * TT + w) * MM + m0) * FF + rem];
    }
    __syncthreads();
    int s = tid / 10, k = tid % 10;
    const float* xrow = xs + s * 320;
    const float* ck = cws + k * 320;
    float r = cb[k];
#pragma unroll
    for (int f = 0; f < 16; f++) {
#pragma unroll
        for (int w = 0; w < 20; w++)
            r += xrow[w * 16 + f] * ck[f * 20 + w];
    }
    const float* clk = clws + k * 160;
    float r0 = clb[k], r1 = clb[k];
#pragma unroll
    for (int f = 0; f < 16; f++) {
#pragma unroll
        for (int j = 0; j < 10; j++) {
            float wv = clk[f * 10 + j];
            r0 += xrow[(2 * j) * 16 + f]     * wv;
            r1 += xrow[(2 * j + 1) * 16 + f] * wv;
        }
    }
    int o = (n0 + s) * 30 + k * 3;
    g_rl[o]     = fmaxf(r, 0.f);
    g_rl[o + 1] = fmaxf(r0, 0.f);
    g_rl[o + 2] = fmaxf(r1, 0.f);
}

// ============================================================================
// Kernel 5: c = sigmoid(a_mx @ Wb + wb); A = adj*c + a_mx*(1-c)
// Tiled SGEMM 64x64, TK=16, 4x4 micro-tile. grid (8,8,8).
// ============================================================================
__global__ void __launch_bounds__(256) gateA_kernel(
    const float* __restrict__ Wb, const float* __restrict__ adj,
    const float* __restrict__ wb)
{
    __shared__ float As[64 * 20];
    __shared__ float Bs[16 * 64];
    int b = blockIdx.z, i0 = blockIdx.y * 64, j0 = blockIdx.x * 64;
    const float* Ab = g_amx + b * MM * MM;
    int tid = threadIdx.x;
    int ty = tid >> 4, tx = tid & 15;
    int lrow = tid >> 2, lkq = (tid & 3) * 4;
    float acc[4][4];
#pragma unroll
    for (int r = 0; r < 4; r++)
#pragma unroll
        for (int c = 0; c < 4; c++) acc[r][c] = 0.f;

    for (int kt = 0; kt < MM; kt += 16) {
        float4 av = *(const float4*)(Ab + (i0 + lrow) * MM + kt + lkq);
        *(float4*)(As + lrow * 20 + lkq) = av;
#pragma unroll
        for (int q = 0; q < 4; q++) {
            int idx = tid + q * 256;
            int r = idx >> 6, c = idx & 63;
            Bs[r * 64 + c] = Wb[(kt + r) * MM + j0 + c];
        }
        __syncthreads();
#pragma unroll
        for (int kk = 0; kk < 16; kk++) {
            float a[4], bb[4];
#pragma unroll
            for (int r = 0; r < 4; r++) a[r] = As[(ty + 16 * r) * 20 + kk];
#pragma unroll
            for (int c = 0; c < 4; c++) bb[c] = Bs[kk * 64 + tx + 16 * c];
#pragma unroll
            for (int r = 0; r < 4; r++)
#pragma unroll
                for (int c = 0; c < 4; c++) acc[r][c] += a[r] * bb[c];
        }
        __syncthreads();
    }
    float wbv = wb[0];
#pragma unroll
    for (int r = 0; r < 4; r++) {
        int i = i0 + ty + 16 * r;
#pragma unroll
        for (int c = 0; c < 4; c++) {
            int j = j0 + tx + 16 * c;
            float cg = fsig(acc[r][c] + wbv);
            float am = Ab[i * MM + j];
            g_A[b * MM * MM + i * MM + j] = adj[i * MM + j] * cg + am * (1.f - cg);
        }
    }
}

// ============================================================================
// Kernel 6: Z = r_l @ gc1_W   (BMx30)@(30x128)
// 128 blocks x 256 thr, 32 nodes each
// ============================================================================
__global__ void __launch_bounds__(256) zk_kernel(const float* __restrict__ gc1_W)
{
    __shared__ float gw[30 * 128];
    __shared__ float rls[32 * 30];
    int tid = threadIdx.x, n0 = blockIdx.x * 32;
    for (int idx = tid; idx < 3840; idx += 256) gw[idx] = gc1_W[idx];
    for (int idx = tid; idx < 960; idx += 256) rls[idx] = g_rl[n0 * 30 + idx];
    __syncthreads();
    int h = tid & 127, sg = tid >> 7;
    float acc[16];
#pragma unroll
    for (int s = 0; s < 16; s++) acc[s] = 0.f;
    for (int q = 0; q < 30; q++) {
        float wv = gw[q * 128 + h];
#pragma unroll
        for (int s = 0; s < 16; s++)
            acc[s] += rls[(sg * 16 + s) * 30 + q] * wv;
    }
#pragma unroll
    for (int s = 0; s < 16; s++)
        g_Z[(n0 + sg * 16 + s) * HH + h] = acc[s];
}

// ============================================================================
// Kernel 7: h1 = relu(A @ Z + gc1_b)  per b: (512x512)@(512x128). grid (2,8,8)
// ============================================================================
__global__ void __launch_bounds__(256) h1_kernel(const float* __restrict__ gc1_b)
{
    __shared__ float As[64 * 20];
    __shared__ float Bs[16 * 64];
    int b = blockIdx.z, i0 = blockIdx.y * 64, j0 = blockIdx.x * 64;
    const float* Ab = g_A + b * MM * MM;
    const float* Zb = g_Z + b * MM * HH;
    int tid = threadIdx.x;
    int ty = tid >> 4, tx = tid & 15;
    int lrow = tid >> 2, lkq = (tid & 3) * 4;
    float acc[4][4];
#pragma unroll
    for (int r = 0; r < 4; r++)
#pragma unroll
        for (int c = 0; c < 4; c++) acc[r][c] = 0.f;

    for (int kt = 0; kt < MM; kt += 16) {
        float4 av = *(const float4*)(Ab + (i0 + lrow) * MM + kt + lkq);
        *(float4*)(As + lrow * 20 + lkq) = av;
#pragma unroll
        for (int q = 0; q < 4; q++) {
            int idx = tid + q * 256;
            int r = idx >> 6, c = idx & 63;
            Bs[r * 64 + c] = Zb[(kt + r) * HH + j0 + c];
        }
        __syncthreads();
#pragma unroll
        for (int kk = 0; kk < 16; kk++) {
            float a[4], bb[4];
#pragma unroll
            for (int r = 0; r < 4; r++) a[r] = As[(ty + 16 * r) * 20 + kk];
#pragma unroll
            for (int c = 0; c < 4; c++) bb[c] = Bs[kk * 64 + tx + 16 * c];
#pragma unroll
            for (int r = 0; r < 4; r++)
#pragma unroll
                for (int c = 0; c < 4; c++) acc[r][c] += a[r] * bb[c];
        }
        __syncthreads();
    }
#pragma unroll
    for (int r = 0; r < 4; r++) {
        int i = i0 + ty + 16 * r;
#pragma unroll
        for (int c = 0; c < 4; c++) {
            int j = j0 + tx + 16 * c;
            g_h1[(b * MM + i) * HH + j] = fmaxf(acc[r][c] + gc1_b[j], 0.f);
        }
    }
}

// ============================================================================
// Kernel 8: Z2 = h1 @ gc2_W  (BMx128)@(128x10). 128 blocks x 320 thr
// ============================================================================
__global__ void __launch_bounds__(320) z2_kernel(const float* __restrict__ gc2_W)
{
    __shared__ float g2[1280];
    __shared__ float h1s[32 * 128];
    int tid = threadIdx.x, n0 = blockIdx.x * 32;
    for (int idx = tid; idx < 1280; idx += 320) g2[idx] = gc2_W[idx];
    for (int idx = tid; idx < 4096; idx += 320) h1s[idx] = g_h1[n0 * HH + idx];
    __syncthreads();
    int s = tid / 10, k = tid % 10;
    float acc = 0.f;
#pragma unroll 8
    for (int j = 0; j < 128; j++)
        acc += h1s[s * 128 + j] * g2[j * 10 + k];
    g_Z2[(n0 + s) * KK + k] = acc;
}

// ============================================================================
// Kernel 9: out_spatial = relu(A @ Z2 + gc2_b)  (512x512)@(512x10)
// grid (16 i-chunks, 8 b) x 320 thr (32 i x 10 k)
// ============================================================================
__global__ void __launch_bounds__(320) spatial_kernel(const float* __restrict__ gc2_b)
{
    __shared__ float z2s[MM * KK];   // 20 KB
    __shared__ float ats[32 * 33];
    int b = blockIdx.y, i0 = blockIdx.x * 32;
    int tid = threadIdx.x;
    for (int idx = tid; idx < MM * KK; idx += 320) z2s[idx] = g_Z2[b * MM * KK + idx];
    int il = tid / 10, k = tid % 10;
    float acc = 0.f;
    for (int j0 = 0; j0 < MM; j0 += 32) {
        __syncthreads();
        for (int idx = tid; idx < 1024; idx += 320) {
            int r = idx >> 5, c = idx & 31;
            ats[r * 33 + c] = g_A[b * MM * MM + (i0 + r) * MM + j0 + c];
        }
        __syncthreads();
#pragma unroll 8
        for (int c = 0; c < 32; c++)
            acc += ats[il * 33 + c] * z2s[(j0 + c) * KK + k];
    }
    g_sp[(b * MM + i0 + il) * KK + k] = fmaxf(acc + gc2_b[k], 0.f);
}

// ============================================================================
// Kernel 10: readout y = [sp, hid] @ out_W^T + out_b ; sigmoid -> out[1..]
// ============================================================================
__global__ void readout_kernel(const float* __restrict__ outW,
                               const float* __restrict__ outb,
                               float* __restrict__ outsig)
{
    __shared__ float ws[138];
    int tid = threadIdx.x;
    if (tid < 138) ws[tid] = outW[tid];
    __syncthreads();
    int n = blockIdx.x * 256 + tid;
    float acc = outb[0];
#pragma unroll
    for (int k = 0; k < 10; k++) acc += g_sp[n * KK + k] * ws[k];
#pragma unroll 4
    for (int h = 0; h < 128; h++) acc += g_hid[n * HH + h] * ws[10 + h];
    g_y[n] = acc;
    outsig[n] = fsig(acc);
}

// Kernel 11: loss = mean(softplus(y) - Y*y) -> out[0]
__global__ void loss_kernel(const float* __restrict__ Y, float* __restrict__ out0)
{
    __shared__ float red[256];
    int tid = threadIdx.x;
    float s = 0.f;
    for (int n = tid; n < BM; n += 256) {
        float v = g_y[n];
        s += fmaxf(v, 0.f) + log1pf(__expf(-fabsf(v))) - Y[n] * v;
    }
    red[tid] = s;
    __syncthreads();
    for (int st = 128; st > 0; st >>= 1) {
        if (tid < st) red[tid] += red[tid + st];
        __syncthreads();
    }
    if (tid == 0) out0[0] = red[0] / (float)BM;
}

// ============================================================================
extern "C" void kernel_launch(void* const* d_in, const int* in_sizes, int n_in,
                              void* d_out, int out_size)
{
    const float* X      = (const float*)d_in[0];
    const float* Y      = (const float*)d_in[1];
    const float* adj    = (const float*)d_in[2];
    const float* V      = (const float*)d_in[3];
    const float* bv     = (const float*)d_in[4];
    const float* W1     = (const float*)d_in[5];
    const float* b1     = (const float*)d_in[6];
    const float* W2     = (const float*)d_in[7];
    const float* Wb     = (const float*)d_in[8];
    const float* wb     = (const float*)d_in[9];
    const float* conv_w = (const float*)d_in[10];
    const float* conv_b = (const float*)d_in[11];
    const float* convl_w= (const float*)d_in[12];
    const float* convl_b= (const float*)d_in[13];
    const float* gWih   = (const float*)d_in[14];
    const float* gWhh   = (const float*)d_in[15];
    const float* gbih   = (const float*)d_in[16];
    const float* gbhh   = (const float*)d_in[17];
    const float* gc1_W  = (const float*)d_in[18];
    const float* gc1_b  = (const float*)d_in[19];
    const float* gc2_W  = (const float*)d_in[20];
    const float* gc2_b  = (const float*)d_in[21];
    const float* out_W  = (const float*)d_in[22];
    const float* out_b  = (const float*)d_in[23];
    float* out = (float*)d_out;

    const int gru_smem = (128 * WTS + 16 * WTS + 16 * 128 + 256) * 4;      // 230976
    const int p_smem   = (128 * 65 * 2 + 4 * 128) * 4;                      // 68608
    cudaFuncSetAttribute(gru_kernel, cudaFuncAttributeMaxDynamicSharedMemorySize, gru_smem);
    cudaFuncSetAttribute(p1p2_kernel, cudaFuncAttributeMaxDynamicSharedMemorySize, p_smem);

    gru_kernel<<<256, 256, gru_smem>>>(X, gWih, gWhh, gbih, gbhh);
    conv_kernel<<<256, 160>>>(X, conv_w, conv_b, convl_w, convl_b);
    p1p2_kernel<<<1024, 256, p_smem>>>(W1, W2);
    amx_kernel<<<dim3(32, 32, 8), 256>>>(b1, V, bv);
    colnorm_kernel<<<dim3(2, 8), 256>>>();
    normdiv_kernel<<<4096, 512>>>();
    gateA_kernel<<<dim3(8, 8, 8), 256>>>(Wb, adj, wb);
    zk_kernel<<<128, 256>>>(gc1_W);
    h1_kernel<<<dim3(2, 8, 8), 256>>>(gc1_b);
    z2_kernel<<<128, 320>>>(gc2_W);
    spatial_kernel<<<dim3(16, 8), 320>>>(gc2_b);
    readout_kernel<<<16, 256>>>(out_W, out_b, out + 1);
    loss_kernel<<<1, 256>>>(Y, out);
}

// round 2
// speedup vs baseline: 1.1487x; 1.1487x over previous
#include <cuda_runtime.h>
#include <cuda_bf16.h>

typedef unsigned long long ull;

// Problem dims
#define BB 8
#define TT 20
#define MM 512
#define FF 16
#define HH 128
#define G3 384
#define BM 4096
#define HALF 64
#define KK 10

// ---------------- scratch ----------------
__device__ __align__(128) float g_hid[BM * HH];
__device__ __align__(128) float g_p1[BM * HALF];
__device__ __align__(128) float g_p2[BM * HALF];
__device__ __align__(128) float g_amx[BB * MM * MM];
__device__ __align__(128) float g_rnrm[BM];
__device__ __align__(128) float g_A[BB * MM * MM];
__device__ __align__(128) float g_rl[BM * 30];
__device__ __align__(128) float g_Z[BM * HH];
__device__ __align__(128) float g_h1[BM * HH];
__device__ __align__(128) float g_Z2[BM * KK];
__device__ __align__(128) float g_sp[BM * KK];
__device__ __align__(128) float g_y[BM];
__device__ __align__(128) float g_wihT[FF * G3];   // transposed Wih [f][g]
__device__ float g_sumV;

// ---------------- helpers ----------------
__device__ __forceinline__ float fsig(float x) {
    return __fdividef(1.f, 1.f + __expf(-x));
}
__device__ __forceinline__ float ftanh(float x) {
    x = fminf(15.f, fmaxf(-15.f, x));
    float t = __expf(2.f * x);
    return __fdividef(t - 1.f, t + 1.f);
}
__device__ __forceinline__ ull fdup(float x) {
    ull r; asm("mov.b64 %0, {%1, %1};" : "=l"(r) : "f"(x)); return r;
}
__device__ __forceinline__ ull fpack(float a, float b) {
    ull r; asm("mov.b64 %0, {%1, %2};" : "=l"(r) : "f"(a), "f"(b)); return r;
}
__device__ __forceinline__ float2 fup(ull v) {
    float2 r; asm("mov.b64 {%0, %1}, %2;" : "=f"(r.x), "=f"(r.y) : "l"(v)); return r;
}
__device__ __forceinline__ void fma2(ull& d, ull a, ull b) {
    asm("fma.rn.f32x2 %0, %1, %2, %0;" : "+l"(d) : "l"(a), "l"(b));
}
__device__ __forceinline__ ull add2(ull a, ull b) {
    ull r; asm("add.rn.f32x2 %0, %1, %2;" : "=l"(r) : "l"(a), "l"(b)); return r;
}

// ============================================================================
// Kernel 0: transpose Wih -> g_wihT[f][g]; also sumV
// ============================================================================
__global__ void wih_t_kernel(const float* __restrict__ Wih,
                             const float* __restrict__ V)
{
    int i = blockIdx.x * 256 + threadIdx.x;
    if (i < G3 * FF) {
        int g = i >> 4, f = i & 15;
        g_wihT[f * G3 + g] = Wih[i];
    }
    if (i == 0) {
        float s = 0.f;
#pragma unroll
        for (int k = 0; k < HALF; k++) s += V[k];
        g_sumV = s;
    }
}

// ============================================================================
// Kernel 1: GRU with fp32x2 packed FMA.
// 128 CTAs x 128 thr. 8 seqs/warp, 32 seqs/CTA. WhhT (128x384) in smem.
// Thread (lane l) owns gate pairs {64p+2l, 64p+2l+1}, p=0,1 per gate type.
// ============================================================================
__global__ void __launch_bounds__(128, 1) gru_kernel(
    const float* __restrict__ X, const float* __restrict__ Whh,
    const float* __restrict__ bih, const float* __restrict__ bhh)
{
    extern __shared__ float sm[];
    float* whhT = sm;             // 128*384 = 49152
    float* hbuf = sm + 49152;     // 128*33  = 4224
    float* xbuf = hbuf + 4224;    // 512

    const int tid = threadIdx.x;
    const int lane = tid & 31;
    const int warp = tid >> 5;
    const int n0 = blockIdx.x * 32;
    const int b = n0 >> 9, m0 = n0 & 511;
    const int sb = warp * 8;

    // transposed Whh load (strided gmem read, conflict-free smem write)
    for (int idx = tid; idx < G3 * HH; idx += 128) {
        int k = idx / G3, g = idx - k * G3;
        whhT[idx] = Whh[g * HH + k];
    }
    for (int idx = tid; idx < 4224; idx += 128) hbuf[idx] = 0.f;

    // biases as pairs
    ull br[2], bz[2], bnx[2], bnh[2];
#pragma unroll
    for (int p = 0; p < 2; p++) {
        int gg = 64 * p + 2 * lane;
        float2 t1 = *(const float2*)(bih + gg);
        float2 t2 = *(const float2*)(bhh + gg);
        br[p] = fpack(t1.x + t2.x, t1.y + t2.y);
        t1 = *(const float2*)(bih + 128 + gg);
        t2 = *(const float2*)(bhh + 128 + gg);
        bz[p] = fpack(t1.x + t2.x, t1.y + t2.y);
        t1 = *(const float2*)(bih + 256 + gg);
        bnx[p] = fpack(t1.x, t1.y);
        t2 = *(const float2*)(bhh + 256 + gg);
        bnh[p] = fpack(t2.x, t2.y);
    }
    __syncthreads();

    for (int t = 0; t < TT; t++) {
        // load x tile (32 seqs x 16 feats)
        for (int i = tid; i < 512; i += 128)
            xbuf[i] = X[((b * TT + t) * MM + m0) * FF + i];
        __syncthreads();

        ull ar[8][2], az[8][2], axn[8][2], ahn[8][2];
#pragma unroll
        for (int s = 0; s < 8; s++)
#pragma unroll
            for (int p = 0; p < 2; p++) {
                ar[s][p] = br[p]; az[s][p] = bz[p];
                axn[s][p] = bnx[p]; ahn[s][p] = bnh[p];
            }

        // x part: gx = Wih @ x (from pre-transposed gmem, L1-hot)
        for (int f = 0; f < FF; f++) {
            const float* wf = g_wihT + f * G3 + 2 * lane;
            ull w0 = *(const ull*)(wf);
            ull w1 = *(const ull*)(wf + 64);
            ull w2 = *(const ull*)(wf + 128);
            ull w3 = *(const ull*)(wf + 192);
            ull w4 = *(const ull*)(wf + 256);
            ull w5 = *(const ull*)(wf + 320);
            const float* xf = xbuf + sb * 16 + f;
#pragma unroll
            for (int s = 0; s < 8; s++) {
                ull xd = fdup(xf[s * 16]);
                fma2(ar[s][0], xd, w0);  fma2(ar[s][1], xd, w1);
                fma2(az[s][0], xd, w2);  fma2(az[s][1], xd, w3);
                fma2(axn[s][0], xd, w4); fma2(axn[s][1], xd, w5);
            }
        }
        // h part
#pragma unroll 2
        for (int k = 0; k < HH; k++) {
            const float* wk = whhT + k * G3 + 2 * lane;
            ull w0 = *(const ull*)(wk);
            ull w1 = *(const ull*)(wk + 64);
            ull w2 = *(const ull*)(wk + 128);
            ull w3 = *(const ull*)(wk + 192);
            ull w4 = *(const ull*)(wk + 256);
            ull w5 = *(const ull*)(wk + 320);
            const float* hk = hbuf + k * 33 + sb;
#pragma unroll
            for (int s = 0; s < 8; s++) {
                ull hd = fdup(hk[s]);
                fma2(ar[s][0], hd, w0);  fma2(ar[s][1], hd, w1);
                fma2(az[s][0], hd, w2);  fma2(az[s][1], hd, w3);
                fma2(ahn[s][0], hd, w4); fma2(ahn[s][1], hd, w5);
            }
        }
        __syncthreads();   // all warps done reading hbuf
        // update
#pragma unroll
        for (int s = 0; s < 8; s++) {
            int col = sb + s;
#pragma unroll
            for (int p = 0; p < 2; p++) {
                int h0 = 64 * p + 2 * lane;
                float2 rv = fup(ar[s][p]);
                float2 zv = fup(az[s][p]);
                float2 xv = fup(axn[s][p]);
                float2 hv = fup(ahn[s][p]);
                float hold0 = hbuf[h0 * 33 + col];
                float hold1 = hbuf[(h0 + 1) * 33 + col];
                float r0 = fsig(rv.x), z0 = fsig(zv.x);
                float nn0 = ftanh(xv.x + r0 * hv.x);
                float r1 = fsig(rv.y), z1 = fsig(zv.y);
                float nn1 = ftanh(xv.y + r1 * hv.y);
                hbuf[h0 * 33 + col]       = nn0 + z0 * (hold0 - nn0);
                hbuf[(h0 + 1) * 33 + col] = nn1 + z1 * (hold1 - nn1);
            }
        }
        __syncthreads();
    }
    for (int idx = tid; idx < 32 * HH; idx += 128) {
        int s = idx >> 7, h = idx & 127;
        g_hid[(n0 + s) * HH + h] = hbuf[h * 33 + s];
    }
}

// ============================================================================
// Kernel 2: p1 = hid@W1^T + b1, p2 = hid@W2^T
// ============================================================================
__global__ void __launch_bounds__(256) p1p2_kernel(
    const float* __restrict__ W1, const float* __restrict__ W2,
    const float* __restrict__ b1)
{
    extern __shared__ float smp[];
    float* w1t = smp;
    float* w2t = w1t + 128 * 65;
    float* hs  = w2t + 128 * 65;
    int tid = threadIdx.x;
    int n0 = blockIdx.x * 4;
    for (int idx = tid; idx < HALF * HH; idx += 256) {
        int k = idx >> 7, h = idx & 127;
        w1t[h * 65 + k] = W1[idx];
        w2t[h * 65 + k] = W2[idx];
    }
    for (int idx = tid; idx < 4 * HH; idx += 256) hs[idx] = g_hid[n0 * HH + idx];
    __syncthreads();
    int s = tid >> 6, kk = tid & 63;
    const float* hr = hs + s * 128;
    float a1 = b1[kk], a2 = 0.f;
#pragma unroll 4
    for (int h = 0; h < 128; h++) {
        float hv = hr[h];
        a1 += hv * w1t[h * 65 + kk];
        a2 += hv * w2t[h * 65 + kk];
    }
    g_p1[(n0 + s) * HALF + kk] = a1;
    g_p2[(n0 + s) * HALF + kk] = a2;
}

// ============================================================================
// Kernel 3: a_mx[b,i,j] = sum_k elu(p1[b,j,k]+p2[b,i,k]) * V[k] + bv
//   elu(v) = max(v,0) + exp(min(v,0)) - 1; the -1*sumV hoisted.
// ============================================================================
__global__ void __launch_bounds__(256) amx_kernel(
    const float* __restrict__ V, const float* __restrict__ bv)
{
    __shared__ float p1t[16 * 66], p2t[16 * 66], Vs[64];
    int b = blockIdx.z, i0 = blockIdx.y * 16, j0 = blockIdx.x * 16;
    int tid = threadIdx.x;
    for (int idx = tid; idx < 16 * 64; idx += 256) {
        int r = idx >> 6, k = idx & 63;
        p1t[r * 66 + k] = g_p1[(b * MM + j0 + r) * HALF + k];
        p2t[r * 66 + k] = g_p2[(b * MM + i0 + r) * HALF + k];
    }
    if (tid < 64) Vs[tid] = V[tid];
    __syncthreads();
    int ii = tid >> 4, jj = tid & 15;
    const float* P1 = p1t + jj * 66;
    const float* P2 = p2t + ii * 66;
    float accp = 0.f, acce = 0.f;
#pragma unroll
    for (int k = 0; k < 64; k += 2) {
        ull a = *(const ull*)(P1 + k);
        ull c = *(const ull*)(P2 + k);
        float2 v = fup(add2(a, c));
        float vk0 = Vs[k], vk1 = Vs[k + 1];
        accp += fmaxf(v.x, 0.f) * vk0;
        acce += __expf(fminf(v.x, 0.f)) * vk0;
        accp += fmaxf(v.y, 0.f) * vk1;
        acce += __expf(fminf(v.y, 0.f)) * vk1;
    }
    g_amx[(b * MM + i0 + ii) * MM + j0 + jj] = accp + acce - g_sumV + bv[0];
}

// Kernel 3b: reciprocal column L2 norms over axis i
__global__ void rnrm_kernel()
{
    int b = blockIdx.y;
    int j = blockIdx.x * 256 + threadIdx.x;
    const float* base = g_amx + b * MM * MM + j;
    float s = 0.f;
#pragma unroll 8
    for (int i = 0; i < MM; i++) { float v = base[i * MM]; s += v * v; }
    g_rnrm[b * MM + j] = 1.f / fmaxf(sqrtf(s), 1e-12f);
}

// ============================================================================
// Kernel 4: conv branch -> r_l (BM x 30) relu
// ============================================================================
__global__ void __launch_bounds__(160) conv_kernel(
    const float* __restrict__ X, const float* __restrict__ cw,
    const float* __restrict__ cb, const float* __restrict__ clw,
    const float* __restrict__ clb)
{
    __shared__ float xs[16 * 320];
    __shared__ float cws[3200];
    __shared__ float clws[1600];
    int tid = threadIdx.x;
    int n0 = blockIdx.x * 16;
    int b = n0 >> 9, m0 = n0 & 511;
    for (int idx = tid; idx < 3200; idx += 160) cws[idx] = cw[idx];
    for (int idx = tid; idx < 1600; idx += 160) clws[idx] = clw[idx];
    for (int idx = tid; idx < 5120; idx += 160) {
        int w = idx >> 8, rem = idx & 255;
        int s = rem >> 4, f = rem & 15;
        xs[s * 320 + w * 16 + f] = X[((b * TT + w) * MM + m0) * FF + rem];
    }
    __syncthreads();
    int s = tid / 10, k = tid % 10;
    const float* xrow = xs + s * 320;
    const float* ck = cws + k * 320;
    float r = cb[k];
#pragma unroll
    for (int f = 0; f < 16; f++)
#pragma unroll
        for (int w = 0; w < 20; w++)
            r += xrow[w * 16 + f] * ck[f * 20 + w];
    const float* clk = clws + k * 160;
    float r0 = clb[k], r1 = clb[k];
#pragma unroll
    for (int f = 0; f < 16; f++)
#pragma unroll
        for (int j = 0; j < 10; j++) {
            float wv = clk[f * 10 + j];
            r0 += xrow[(2 * j) * 16 + f]     * wv;
            r1 += xrow[(2 * j + 1) * 16 + f] * wv;
        }
    int o = (n0 + s) * 30 + k * 3;
    g_rl[o]     = fmaxf(r, 0.f);
    g_rl[o + 1] = fmaxf(r0, 0.f);
    g_rl[o + 2] = fmaxf(r1, 0.f);
}

// ============================================================================
// Kernel 5: gateA (fp32x2, normalize folded in):
//   c = sigmoid((amx*rn) @ Wb + wb); A = adj*c + amx*rn*(1-c)
// ============================================================================
__global__ void __launch_bounds__(256) gateA_kernel(
    const float* __restrict__ Wb, const float* __restrict__ adj,
    const float* __restrict__ wb)
{
    __shared__ ull Asd[64 * 17];
    __shared__ float Bs[16 * 64];
    int b = blockIdx.z, i0 = blockIdx.y * 64, j0 = blockIdx.x * 64;
    const float* Ab = g_amx + b * MM * MM;
    const float* rn = g_rnrm + b * MM;
    int tid = threadIdx.x;
    int ty = tid >> 4, tx = tid & 15;
    int lrow = tid >> 2, lkq = (tid & 3) * 4;
    ull acc[4][2];
#pragma unroll
    for (int r = 0; r < 4; r++) { acc[r][0] = 0ULL; acc[r][1] = 0ULL; }

    for (int kt = 0; kt < MM; kt += 16) {
        float4 av = *(const float4*)(Ab + (i0 + lrow) * MM + kt + lkq);
        float4 rv = *(const float4*)(rn + kt + lkq);
        av.x *= rv.x; av.y *= rv.y; av.z *= rv.z; av.w *= rv.w;
        Asd[lrow * 17 + lkq]     = fdup(av.x);
        Asd[lrow * 17 + lkq + 1] = fdup(av.y);
        Asd[lrow * 17 + lkq + 2] = fdup(av.z);
        Asd[lrow * 17 + lkq + 3] = fdup(av.w);
#pragma unroll
        for (int q = 0; q < 4; q++) {
            int idx = tid + q * 256;
            int r = idx >> 6, c = idx & 63;
            Bs[r * 64 + c] = Wb[(kt + r) * MM + j0 + c];
        }
        __syncthreads();
#pragma unroll
        for (int kk = 0; kk < 16; kk++) {
            ull b0 = *(const ull*)&Bs[kk * 64 + 2 * tx];
            ull b1 = *(const ull*)&Bs[kk * 64 + 32 + 2 * tx];
#pragma unroll
            for (int r = 0; r < 4; r++) {
                ull a = Asd[(ty + 16 * r) * 17 + kk];
                fma2(acc[r][0], a, b0);
                fma2(acc[r][1], a, b1);
            }
        }
        __syncthreads();
    }
    float wbv = wb[0];
#pragma unroll
    for (int r = 0; r < 4; r++) {
        int i = i0 + ty + 16 * r;
#pragma unroll
        for (int c2 = 0; c2 < 2; c2++) {
            int j = j0 + 2 * tx + 32 * c2;
            float2 val = fup(acc[r][c2]);
            float2 ax = *(const float2*)(Ab + i * MM + j);
            float2 rv2 = *(const float2*)(rn + j);
            float2 aj = *(const float2*)(adj + i * MM + j);
            float cg0 = fsig(val.x + wbv);
            float cg1 = fsig(val.y + wbv);
            float2 ov;
            ov.x = aj.x * cg0 + ax.x * rv2.x * (1.f - cg0);
            ov.y = aj.y * cg1 + ax.y * rv2.y * (1.f - cg1);
            *(float2*)(g_A + b * MM * MM + i * MM + j) = ov;
        }
    }
}

// ============================================================================
// Kernel 6: Z = r_l @ gc1_W
// ============================================================================
__global__ void __launch_bounds__(256) zk_kernel(const float* __restrict__ gc1_W)
{
    __shared__ float gw[30 * 128];
    __shared__ float rls[32 * 30];
    int tid = threadIdx.x, n0 = blockIdx.x * 32;
    for (int idx = tid; idx < 3840; idx += 256) gw[idx] = gc1_W[idx];
    for (int idx = tid; idx < 960; idx += 256) rls[idx] = g_rl[n0 * 30 + idx];
    __syncthreads();
    int h = tid & 127, sg = tid >> 7;
    float acc[16];
#pragma unroll
    for (int s = 0; s < 16; s++) acc[s] = 0.f;
    for (int q = 0; q < 30; q++) {
        float wv = gw[q * 128 + h];
#pragma unroll
        for (int s = 0; s < 16; s++)
            acc[s] += rls[(sg * 16 + s) * 30 + q] * wv;
    }
#pragma unroll
    for (int s = 0; s < 16; s++)
        g_Z[(n0 + sg * 16 + s) * HH + h] = acc[s];
}

// ============================================================================
// Kernel 7: h1 = relu(A @ Z + gc1_b)   fp32x2
// ============================================================================
__global__ void __launch_bounds__(256) h1_kernel(const float* __restrict__ gc1_b)
{
    __shared__ ull Asd[64 * 17];
    __shared__ float Bs[16 * 64];
    int b = blockIdx.z, i0 = blockIdx.y * 64, j0 = blockIdx.x * 64;
    const float* Ab = g_A + b * MM * MM;
    const float* Zb = g_Z + b * MM * HH;
    int tid = threadIdx.x;
    int ty = tid >> 4, tx = tid & 15;
    int lrow = tid >> 2, lkq = (tid & 3) * 4;
    ull acc[4][2];
#pragma unroll
    for (int r = 0; r < 4; r++) { acc[r][0] = 0ULL; acc[r][1] = 0ULL; }

    for (int kt = 0; kt < MM; kt += 16) {
        float4 av = *(const float4*)(Ab + (i0 + lrow) * MM + kt + lkq);
        Asd[lrow * 17 + lkq]     = fdup(av.x);
        Asd[lrow * 17 + lkq + 1] = fdup(av.y);
        Asd[lrow * 17 + lkq + 2] = fdup(av.z);
        Asd[lrow * 17 + lkq + 3] = fdup(av.w);
#pragma unroll
        for (int q = 0; q < 4; q++) {
            int idx = tid + q * 256;
            int r = idx >> 6, c = idx & 63;
            Bs[r * 64 + c] = Zb[(kt + r) * HH + j0 + c];
        }
        __syncthreads();
#pragma unroll
        for (int kk = 0; kk < 16; kk++) {
            ull b0 = *(const ull*)&Bs[kk * 64 + 2 * tx];
            ull b1 = *(const ull*)&Bs[kk * 64 + 32 + 2 * tx];
#pragma unroll
            for (int r = 0; r < 4; r++) {
                ull a = Asd[(ty + 16 * r) * 17 + kk];
                fma2(acc[r][0], a, b0);
                fma2(acc[r][1], a, b1);
            }
        }
        __syncthreads();
    }
#pragma unroll
    for (int r = 0; r < 4; r++) {
        int i = i0 + ty + 16 * r;
#pragma unroll
        for (int c2 = 0; c2 < 2; c2++) {
            int j = j0 + 2 * tx + 32 * c2;
            float2 val = fup(acc[r][c2]);
            g_h1[(b * MM + i) * HH + j]     = fmaxf(val.x + gc1_b[j], 0.f);
            g_h1[(b * MM + i) * HH + j + 1] = fmaxf(val.y + gc1_b[j + 1], 0.f);
        }
    }
}

// ============================================================================
// Kernel 8: Z2 = h1 @ gc2_W
// ============================================================================
__global__ void __launch_bounds__(320) z2_kernel(const float* __restrict__ gc2_W)
{
    __shared__ float g2[1280];
    __shared__ float h1s[32 * 128];
    int tid = threadIdx.x, n0 = blockIdx.x * 32;
    for (int idx = tid; idx < 1280; idx += 320) g2[idx] = gc2_W[idx];
    for (int idx = tid; idx < 4096; idx += 320) h1s[idx] = g_h1[n0 * HH + idx];
    __syncthreads();
    int s = tid / 10, k = tid % 10;
    float acc = 0.f;
#pragma unroll 8
    for (int j = 0; j < 128; j++)
        acc += h1s[s * 128 + j] * g2[j * 10 + k];
    g_Z2[(n0 + s) * KK + k] = acc;
}

// ============================================================================
// Kernel 9: out_spatial = relu(A @ Z2 + gc2_b)
// ============================================================================
__global__ void __launch_bounds__(320) spatial_kernel(const float* __restrict__ gc2_b)
{
    __shared__ float z2s[MM * KK];
    __shared__ float ats[32 * 33];
    int b = blockIdx.y, i0 = blockIdx.x * 32;
    int tid = threadIdx.x;
    for (int idx = tid; idx < MM * KK; idx += 320) z2s[idx] = g_Z2[b * MM * KK + idx];
    int il = tid / 10, k = tid % 10;
    float acc = 0.f;
    for (int j0 = 0; j0 < MM; j0 += 32) {
        __syncthreads();
        for (int idx = tid; idx < 1024; idx += 320) {
            int r = idx >> 5, c = idx & 31;
            ats[r * 33 + c] = g_A[b * MM * MM + (i0 + r) * MM + j0 + c];
        }
        __syncthreads();
#pragma unroll 8
        for (int c = 0; c < 32; c++)
            acc += ats[il * 33 + c] * z2s[(j0 + c) * KK + k];
    }
    g_sp[(b * MM + i0 + il) * KK + k] = fmaxf(acc + gc2_b[k], 0.f);
}

// ============================================================================
// Kernel 10: readout
// ============================================================================
__global__ void readout_kernel(const float* __restrict__ outW,
                               const float* __restrict__ outb,
                               float* __restrict__ outsig)
{
    __shared__ float ws[138];
    int tid = threadIdx.x;
    if (tid < 138) ws[tid] = outW[tid];
    __syncthreads();
    int n = blockIdx.x * 256 + tid;
    float acc = outb[0];
#pragma unroll
    for (int k = 0; k < 10; k++) acc += g_sp[n * KK + k] * ws[k];
#pragma unroll 4
    for (int h = 0; h < 128; h++) acc += g_hid[n * HH + h] * ws[10 + h];
    g_y[n] = acc;
    outsig[n] = fsig(acc);
}

// Kernel 11: loss
__global__ void loss_kernel(const float* __restrict__ Y, float* __restrict__ out0)
{
    __shared__ float red[256];
    int tid = threadIdx.x;
    float s = 0.f;
    for (int n = tid; n < BM; n += 256) {
        float v = g_y[n];
        s += fmaxf(v, 0.f) + log1pf(__expf(-fabsf(v))) - Y[n] * v;
    }
    red[tid] = s;
    __syncthreads();
    for (int st = 128; st > 0; st >>= 1) {
        if (tid < st) red[tid] += red[tid + st];
        __syncthreads();
    }
    if (tid == 0) out0[0] = red[0] / (float)BM;
}

// ============================================================================
extern "C" void kernel_launch(void* const* d_in, const int* in_sizes, int n_in,
                              void* d_out, int out_size)
{
    const float* X      = (const float*)d_in[0];
    const float* Y      = (const float*)d_in[1];
    const float* adj    = (const float*)d_in[2];
    const float* V      = (const float*)d_in[3];
    const float* bv     = (const float*)d_in[4];
    const float* W1     = (const float*)d_in[5];
    const float* b1     = (const float*)d_in[6];
    const float* W2     = (const float*)d_in[7];
    const float* Wb     = (const float*)d_in[8];
    const float* wb     = (const float*)d_in[9];
    const float* conv_w = (const float*)d_in[10];
    const float* conv_b = (const float*)d_in[11];
    const float* convl_w= (const float*)d_in[12];
    const float* convl_b= (const float*)d_in[13];
    const float* gWih   = (const float*)d_in[14];
    const float* gWhh   = (const float*)d_in[15];
    const float* gbih   = (const float*)d_in[16];
    const float* gbhh   = (const float*)d_in[17];
    const float* gc1_W  = (const float*)d_in[18];
    const float* gc1_b  = (const float*)d_in[19];
    const float* gc2_W  = (const float*)d_in[20];
    const float* gc2_b  = (const float*)d_in[21];
    const float* out_W  = (const float*)d_in[22];
    const float* out_b  = (const float*)d_in[23];
    float* out = (float*)d_out;

    const int gru_smem = (49152 + 4224 + 512) * 4;         // 215552
    const int p_smem   = (128 * 65 * 2 + 4 * 128) * 4;
    cudaFuncSetAttribute(gru_kernel, cudaFuncAttributeMaxDynamicSharedMemorySize, gru_smem);
    cudaFuncSetAttribute(p1p2_kernel, cudaFuncAttributeMaxDynamicSharedMemorySize, p_smem);

    wih_t_kernel<<<24, 256>>>(gWih, V);
    gru_kernel<<<128, 128, gru_smem>>>(X, gWhh, gbih, gbhh);
    conv_kernel<<<256, 160>>>(X, conv_w, conv_b, convl_w, convl_b);
    p1p2_kernel<<<1024, 256, p_smem>>>(W1, W2, b1);
    amx_kernel<<<dim3(32, 32, 8), 256>>>(V, bv);
    rnrm_kernel<<<dim3(2, 8), 256>>>();
    gateA_kernel<<<dim3(8, 8, 8), 256>>>(Wb, adj, wb);
    zk_kernel<<<128, 256>>>(gc1_W);
    h1_kernel<<<dim3(2, 8, 8), 256>>>(gc1_b);
    z2_kernel<<<128, 320>>>(gc2_W);
    spatial_kernel<<<dim3(16, 8), 320>>>(gc2_b);
    readout_kernel<<<16, 256>>>(out_W, out_b, out + 1);
    loss_kernel<<<1, 256>>>(Y, out);
}

// round 3
// speedup vs baseline: 1.2408x; 1.0802x over previous
#include <cuda_runtime.h>
#include <cuda_bf16.h>

typedef unsigned long long ull;

#define BB 8
#define TT 20
#define MM 512
#define FF 16
#define HH 128
#define G3 384
#define BM 4096
#define HALF 64
#define KK 10

// ---------------- scratch ----------------
__device__ __align__(128) float g_hid[BM * HH];
__device__ __align__(128) float g_p1[BM * HALF];
__device__ __align__(128) float g_p2[BM * HALF];
__device__ __align__(128) float g_e1[BM * HALF];
__device__ __align__(128) float g_e2[BM * HALF];
__device__ __align__(128) float g_amx[BB * MM * MM];
__device__ __align__(128) float g_rnrm[BM];
__device__ __align__(128) float g_A[BB * MM * MM];
__device__ __align__(128) float g_rl[BM * 30];
__device__ __align__(128) float g_Z[BM * HH];
__device__ __align__(128) float g_h1[BM * HH];
__device__ __align__(128) float g_Z2[BM * KK];
__device__ __align__(128) float g_sp[BM * KK];
__device__ __align__(128) float g_y[BM];
__device__ __align__(128) float g_wih4[FF * G3];   // permuted Wih [f][wq][lane][4]
__device__ float g_sumV;

// ---------------- helpers ----------------
__device__ __forceinline__ float fsig(float x) {
    return __fdividef(1.f, 1.f + __expf(-x));
}
__device__ __forceinline__ float ftanh(float x) {
    x = fminf(15.f, fmaxf(-15.f, x));
    float t = __expf(2.f * x);
    return __fdividef(t - 1.f, t + 1.f);
}
__device__ __forceinline__ ull fdup(float x) {
    ull r; asm("mov.b64 %0, {%1, %1};" : "=l"(r) : "f"(x)); return r;
}
__device__ __forceinline__ float2 fup(ull v) {
    float2 r; asm("mov.b64 {%0, %1}, %2;" : "=f"(r.x), "=f"(r.y) : "l"(v)); return r;
}
__device__ __forceinline__ void fma2(ull& d, ull a, ull b) {
    asm("fma.rn.f32x2 %0, %1, %2, %0;" : "+l"(d) : "l"(a), "l"(b));
}
__device__ __forceinline__ ull add2(ull a, ull b) {
    ull r; asm("add.rn.f32x2 %0, %1, %2;" : "=l"(r) : "l"(a), "l"(b)); return r;
}
__device__ __forceinline__ ull mul2(ull a, ull b) {
    ull r; asm("mul.rn.f32x2 %0, %1, %2;" : "=l"(r) : "l"(a), "l"(b)); return r;
}

// ============================================================================
// Kernel 0: permute Wih -> g_wih4[f][wq][lane][4]; also sumV
// ============================================================================
__global__ void wih_t_kernel(const float* __restrict__ Wih,
                             const float* __restrict__ V)
{
    int i = blockIdx.x * 256 + threadIdx.x;
    if (i < G3 * FF) {
        int f = i / G3, rem = i % G3;
        int wq = rem >> 7, r2 = rem & 127;
        int lane = r2 >> 2, e = r2 & 3;
        int g = wq * 128 + ((e >> 1) * 64) + 2 * lane + (e & 1);
        g_wih4[i] = Wih[g * FF + f];
    }
    if (i == 0) {
        float s = 0.f;
#pragma unroll
        for (int k = 0; k < HALF; k++) s += V[k];
        g_sumV = s;
    }
}

// ============================================================================
// Kernel 1: GRU. 128 CTAs x 256 thr (8 warps x 4 seqs). fp32x2 FMA.
// Whh permuted in smem: [k][wq(3)][lane(32)][4floats] -> 3x LDS.128/thread/k.
// ============================================================================
#define HS 36
__global__ void __launch_bounds__(256, 1) gru_kernel(
    const float* __restrict__ X, const float* __restrict__ Whh,
    const float* __restrict__ bih, const float* __restrict__ bhh)
{
    extern __shared__ float sm[];
    float* whh4 = sm;                 // 128*384 = 49152
    float* hbuf = sm + 49152;         // 128*36  = 4608
    float* xbuf = hbuf + 128 * HS;    // 512

    const int tid = threadIdx.x;
    const int lane = tid & 31;
    const int warp = tid >> 5;
    const int n0 = blockIdx.x * 32;
    const int b = n0 >> 9, m0 = n0 & 511;
    const int sb = warp * 4;

    // permuted Whh: dst[k][wq][lane][4] = Whh[g][k]
    for (int idx = tid; idx < G3 * HH; idx += 256) {
        int k = idx / G3, rem = idx - k * G3;
        int wq = rem >> 7, r2 = rem & 127;
        int ln = r2 >> 2, e = r2 & 3;
        int g = wq * 128 + ((e >> 1) * 64) + 2 * ln + (e & 1);
        whh4[idx] = Whh[g * HH + k];
    }
    for (int idx = tid; idx < 128 * HS; idx += 256) hbuf[idx] = 0.f;

    ull br[2], bz[2], bnx[2], bnh[2];
#pragma unroll
    for (int p = 0; p < 2; p++) {
        int gg = 64 * p + 2 * lane;
        float2 t1 = *(const float2*)(bih + gg);
        float2 t2 = *(const float2*)(bhh + gg);
        br[p] = add2(*(const ull*)&t1, *(const ull*)&t2);
        t1 = *(const float2*)(bih + 128 + gg);
        t2 = *(const float2*)(bhh + 128 + gg);
        bz[p] = add2(*(const ull*)&t1, *(const ull*)&t2);
        t1 = *(const float2*)(bih + 256 + gg);
        bnx[p] = *(const ull*)&t1;
        t2 = *(const float2*)(bhh + 256 + gg);
        bnh[p] = *(const ull*)&t2;
    }
    __syncthreads();

    for (int t = 0; t < TT; t++) {
        for (int i = tid; i < 512; i += 256)
            xbuf[i] = X[((b * TT + t) * MM + m0) * FF + i];
        __syncthreads();

        ull ar[4][2], az[4][2], axn[4][2], ahn[4][2];
#pragma unroll
        for (int s = 0; s < 4; s++)
#pragma unroll
            for (int p = 0; p < 2; p++) {
                ar[s][p] = br[p]; az[s][p] = bz[p];
                axn[s][p] = bnx[p]; ahn[s][p] = bnh[p];
            }

        // x part
#pragma unroll 4
        for (int f = 0; f < FF; f++) {
            const float* wf = g_wih4 + f * G3 + lane * 4;
            ulonglong2 w01 = *(const ulonglong2*)(wf);
            ulonglong2 w23 = *(const ulonglong2*)(wf + 128);
            ulonglong2 w45 = *(const ulonglong2*)(wf + 256);
            const float* xf = xbuf + sb * 16 + f;
#pragma unroll
            for (int s = 0; s < 4; s++) {
                ull xd = fdup(xf[s * 16]);
                fma2(ar[s][0], xd, w01.x);  fma2(ar[s][1], xd, w01.y);
                fma2(az[s][0], xd, w23.x);  fma2(az[s][1], xd, w23.y);
                fma2(axn[s][0], xd, w45.x); fma2(axn[s][1], xd, w45.y);
            }
        }
        // h part
#pragma unroll 2
        for (int k = 0; k < HH; k++) {
            const float* wk = whh4 + k * G3 + lane * 4;
            ulonglong2 w01 = *(const ulonglong2*)(wk);
            ulonglong2 w23 = *(const ulonglong2*)(wk + 128);
            ulonglong2 w45 = *(const ulonglong2*)(wk + 256);
            float4 h4 = *(const float4*)(hbuf + k * HS + sb);
            ull hd0 = fdup(h4.x), hd1 = fdup(h4.y);
            ull hd2 = fdup(h4.z), hd3 = fdup(h4.w);
            fma2(ar[0][0], hd0, w01.x);  fma2(ar[0][1], hd0, w01.y);
            fma2(az[0][0], hd0, w23.x);  fma2(az[0][1], hd0, w23.y);
            fma2(ahn[0][0], hd0, w45.x); fma2(ahn[0][1], hd0, w45.y);
            fma2(ar[1][0], hd1, w01.x);  fma2(ar[1][1], hd1, w01.y);
            fma2(az[1][0], hd1, w23.x);  fma2(az[1][1], hd1, w23.y);
            fma2(ahn[1][0], hd1, w45.x); fma2(ahn[1][1], hd1, w45.y);
            fma2(ar[2][0], hd2, w01.x);  fma2(ar[2][1], hd2, w01.y);
            fma2(az[2][0], hd2, w23.x);  fma2(az[2][1], hd2, w23.y);
            fma2(ahn[2][0], hd2, w45.x); fma2(ahn[2][1], hd2, w45.y);
            fma2(ar[3][0], hd3, w01.x);  fma2(ar[3][1], hd3, w01.y);
            fma2(az[3][0], hd3, w23.x);  fma2(az[3][1], hd3, w23.y);
            fma2(ahn[3][0], hd3, w45.x); fma2(ahn[3][1], hd3, w45.y);
        }
        __syncthreads();   // all reads of hbuf done
#pragma unroll
        for (int s = 0; s < 4; s++) {
            int col = sb + s;
#pragma unroll
            for (int p = 0; p < 2; p++) {
                int h0 = 64 * p + 2 * lane;
                float2 rv = fup(ar[s][p]);
                float2 zv = fup(az[s][p]);
                float2 xv = fup(axn[s][p]);
                float2 hv = fup(ahn[s][p]);
                float hold0 = hbuf[h0 * HS + col];
                float hold1 = hbuf[(h0 + 1) * HS + col];
                float r0 = fsig(rv.x), z0 = fsig(zv.x);
                float nn0 = ftanh(xv.x + r0 * hv.x);
                float r1 = fsig(rv.y), z1 = fsig(zv.y);
                float nn1 = ftanh(xv.y + r1 * hv.y);
                hbuf[h0 * HS + col]       = nn0 + z0 * (hold0 - nn0);
                hbuf[(h0 + 1) * HS + col] = nn1 + z1 * (hold1 - nn1);
            }
        }
        __syncthreads();
    }
    for (int idx = tid; idx < 32 * HH; idx += 256) {
        int s = idx >> 7, h = idx & 127;
        g_hid[(n0 + s) * HH + h] = hbuf[h * HS + s];
    }
}

// ============================================================================
// Kernel 2: p1 = hid@W1^T + b1, p2 = hid@W2^T; also e1=exp(p1), e2=exp(p2).
// 128 blocks x 256 thr, 32 nodes/block, weights loaded once.
// ============================================================================
__global__ void __launch_bounds__(256) p1p2_kernel(
    const float* __restrict__ W1, const float* __restrict__ W2,
    const float* __restrict__ b1)
{
    extern __shared__ float smp[];
    float* w1t = smp;              // [h][k] 128*64
    float* w2t = w1t + 8192;       // 128*64
    float* hs  = w2t + 8192;       // 32*128
    int tid = threadIdx.x;
    int n0 = blockIdx.x * 32;
    for (int idx = tid; idx < HALF * HH; idx += 256) {
        int k = idx >> 7, h = idx & 127;
        w1t[h * 64 + k] = W1[idx];
        w2t[h * 64 + k] = W2[idx];
    }
    for (int idx = tid; idx < 32 * HH; idx += 256) hs[idx] = g_hid[n0 * HH + idx];
    __syncthreads();
    int kk = tid & 63, grp = tid >> 6;
    float a1[8], a2[8];
    float bk = b1[kk];
#pragma unroll
    for (int s = 0; s < 8; s++) { a1[s] = bk; a2[s] = 0.f; }
#pragma unroll 4
    for (int h = 0; h < 128; h++) {
        float wa = w1t[h * 64 + kk];
        float wc = w2t[h * 64 + kk];
        const float* hp = hs + (grp * 8) * 128 + h;
#pragma unroll
        for (int s = 0; s < 8; s++) {
            float hv = hp[s * 128];
            a1[s] += hv * wa;
            a2[s] += hv * wc;
        }
    }
#pragma unroll
    for (int s = 0; s < 8; s++) {
        int node = n0 + grp * 8 + s;
        float p1 = a1[s], p2 = a2[s];
        g_p1[node * 64 + kk] = p1;
        g_e1[node * 64 + kk] = __expf(fminf(p1, 60.f));
        g_p2[node * 64 + kk] = p2;
        g_e2[node * 64 + kk] = __expf(fminf(p2, 60.f));
    }
}

// ============================================================================
// Kernel 3: a_mx[b,i,j] = sum_k [max(v,0) + min(e1*e2,1)]*V[k] - sumV + bv
//   where v = p1[j,k]+p2[i,k]; no MUFU in the O(M^2) loop.
// 64x64 tile per 256-thr block, 4x4 micro. grid (8,8,8).
// ============================================================================
__global__ void __launch_bounds__(256) amx_kernel(
    const float* __restrict__ V, const float* __restrict__ bv)
{
    extern __shared__ float sma[];
    float* p1s = sma;               // [j][66]
    float* e1s = p1s + 64 * 66;
    float* p2s = e1s + 64 * 66;     // [i][66]
    float* e2s = p2s + 64 * 66;
    float* Vs  = e2s + 64 * 66;     // 64
    int b = blockIdx.z, i0 = blockIdx.y * 64, j0 = blockIdx.x * 64;
    int tid = threadIdx.x;
    for (int idx = tid; idx < 64 * 64; idx += 256) {
        int r = idx >> 6, k = idx & 63;
        p1s[r * 66 + k] = g_p1[(b * MM + j0 + r) * HALF + k];
        e1s[r * 66 + k] = g_e1[(b * MM + j0 + r) * HALF + k];
        p2s[r * 66 + k] = g_p2[(b * MM + i0 + r) * HALF + k];
        e2s[r * 66 + k] = g_e2[(b * MM + i0 + r) * HALF + k];
    }
    if (tid < 64) Vs[tid] = V[tid];
    __syncthreads();
    int tyy = tid >> 4, txx = tid & 15;
    float accp[4][4], acce[4][4];
#pragma unroll
    for (int r = 0; r < 4; r++)
#pragma unroll
        for (int c = 0; c < 4; c++) { accp[r][c] = 0.f; acce[r][c] = 0.f; }

#pragma unroll 2
    for (int kp = 0; kp < 32; kp++) {
        int k = 2 * kp;
        float vk0 = Vs[k], vk1 = Vs[k + 1];
        ull p2r[4], e2r[4], p1c[4], e1c[4];
#pragma unroll
        for (int r = 0; r < 4; r++) {
            p2r[r] = *(const ull*)&p2s[(tyy + 16 * r) * 66 + k];
            e2r[r] = *(const ull*)&e2s[(tyy + 16 * r) * 66 + k];
        }
#pragma unroll
        for (int c = 0; c < 4; c++) {
            p1c[c] = *(const ull*)&p1s[(txx + 16 * c) * 66 + k];
            e1c[c] = *(const ull*)&e1s[(txx + 16 * c) * 66 + k];
        }
#pragma unroll
        for (int r = 0; r < 4; r++)
#pragma unroll
            for (int c = 0; c < 4; c++) {
                float2 v = fup(add2(p1c[c], p2r[r]));
                float2 m = fup(mul2(e1c[c], e2r[r]));
                accp[r][c] = fmaf(fmaxf(v.x, 0.f), vk0, accp[r][c]);
                accp[r][c] = fmaf(fmaxf(v.y, 0.f), vk1, accp[r][c]);
                acce[r][c] = fmaf(fminf(m.x, 1.f), vk0, acce[r][c]);
                acce[r][c] = fmaf(fminf(m.y, 1.f), vk1, acce[r][c]);
            }
    }
    float cst = bv[0] - g_sumV;
#pragma unroll
    for (int r = 0; r < 4; r++) {
        int i = i0 + tyy + 16 * r;
#pragma unroll
        for (int c = 0; c < 4; c++) {
            int j = j0 + txx + 16 * c;
            g_amx[(b * MM + i) * MM + j] = accp[r][c] + acce[r][c] + cst;
        }
    }
}

// Kernel 3b: reciprocal column L2 norms (coalesced rows)
__global__ void __launch_bounds__(256) rnrm_kernel()
{
    __shared__ float red[256];
    int b = blockIdx.y;
    int jt = blockIdx.x * 128;
    int tj = threadIdx.x & 127, half = threadIdx.x >> 7;
    const float* base = g_amx + b * MM * MM + jt + tj;
    float s = 0.f;
#pragma unroll 8
    for (int i = half * 256; i < half * 256 + 256; i++) {
        float v = base[i * MM]; s += v * v;
    }
    red[threadIdx.x] = s;
    __syncthreads();
    if (half == 0) {
        float tot = red[tj] + red[tj + 128];
        g_rnrm[b * MM + jt + tj] = 1.f / fmaxf(sqrtf(tot), 1e-12f);
    }
}

// ============================================================================
// Kernel 4: conv branch -> r_l (BM x 30) relu
// ============================================================================
__global__ void __launch_bounds__(160) conv_kernel(
    const float* __restrict__ X, const float* __restrict__ cw,
    const float* __restrict__ cb, const float* __restrict__ clw,
    const float* __restrict__ clb)
{
    __shared__ float xs[16 * 320];
    __shared__ float cws[3200];
    __shared__ float clws[1600];
    int tid = threadIdx.x;
    int n0 = blockIdx.x * 16;
    int b = n0 >> 9, m0 = n0 & 511;
    for (int idx = tid; idx < 3200; idx += 160) cws[idx] = cw[idx];
    for (int idx = tid; idx < 1600; idx += 160) clws[idx] = clw[idx];
    for (int idx = tid; idx < 5120; idx += 160) {
        int w = idx >> 8, rem = idx & 255;
        int s = rem >> 4, f = rem & 15;
        xs[s * 320 + w * 16 + f] = X[((b * TT + w) * MM + m0) * FF + rem];
    }
    __syncthreads();
    int s = tid / 10, k = tid % 10;
    const float* xrow = xs + s * 320;
    const float* ck = cws + k * 320;
    float r = cb[k];
#pragma unroll
    for (int f = 0; f < 16; f++)
#pragma unroll
        for (int w = 0; w < 20; w++)
            r += xrow[w * 16 + f] * ck[f * 20 + w];
    const float* clk = clws + k * 160;
    float r0 = clb[k], r1 = clb[k];
#pragma unroll
    for (int f = 0; f < 16; f++)
#pragma unroll
        for (int j = 0; j < 10; j++) {
            float wv = clk[f * 10 + j];
            r0 += xrow[(2 * j) * 16 + f]     * wv;
            r1 += xrow[(2 * j + 1) * 16 + f] * wv;
        }
    int o = (n0 + s) * 30 + k * 3;
    g_rl[o]     = fmaxf(r, 0.f);
    g_rl[o + 1] = fmaxf(r0, 0.f);
    g_rl[o + 2] = fmaxf(r1, 0.f);
}

// ============================================================================
// Kernel 5: gateA (fp32x2, normalize folded in)
// ============================================================================
__global__ void __launch_bounds__(256) gateA_kernel(
    const float* __restrict__ Wb, const float* __restrict__ adj,
    const float* __restrict__ wb)
{
    __shared__ ull Asd[64 * 17];
    __shared__ float Bs[16 * 64];
    int b = blockIdx.z, i0 = blockIdx.y * 64, j0 = blockIdx.x * 64;
    const float* Ab = g_amx + b * MM * MM;
    const float* rn = g_rnrm + b * MM;
    int tid = threadIdx.x;
    int ty = tid >> 4, tx = tid & 15;
    int lrow = tid >> 2, lkq = (tid & 3) * 4;
    ull acc[4][2];
#pragma unroll
    for (int r = 0; r < 4; r++) { acc[r][0] = 0ULL; acc[r][1] = 0ULL; }

    for (int kt = 0; kt < MM; kt += 16) {
        float4 av = *(const float4*)(Ab + (i0 + lrow) * MM + kt + lkq);
        float4 rv = *(const float4*)(rn + kt + lkq);
        av.x *= rv.x; av.y *= rv.y; av.z *= rv.z; av.w *= rv.w;
        Asd[lrow * 17 + lkq]     = fdup(av.x);
        Asd[lrow * 17 + lkq + 1] = fdup(av.y);
        Asd[lrow * 17 + lkq + 2] = fdup(av.z);
        Asd[lrow * 17 + lkq + 3] = fdup(av.w);
#pragma unroll
        for (int q = 0; q < 4; q++) {
            int idx = tid + q * 256;
            int r = idx >> 6, c = idx & 63;
            Bs[r * 64 + c] = Wb[(kt + r) * MM + j0 + c];
        }
        __syncthreads();
#pragma unroll
        for (int kk = 0; kk < 16; kk++) {
            ull b0 = *(const ull*)&Bs[kk * 64 + 2 * tx];
            ull b1 = *(const ull*)&Bs[kk * 64 + 32 + 2 * tx];
#pragma unroll
            for (int r = 0; r < 4; r++) {
                ull a = Asd[(ty + 16 * r) * 17 + kk];
                fma2(acc[r][0], a, b0);
                fma2(acc[r][1], a, b1);
            }
        }
        __syncthreads();
    }
    float wbv = wb[0];
#pragma unroll
    for (int r = 0; r < 4; r++) {
        int i = i0 + ty + 16 * r;
#pragma unroll
        for (int c2 = 0; c2 < 2; c2++) {
            int j = j0 + 2 * tx + 32 * c2;
            float2 val = fup(acc[r][c2]);
            float2 ax = *(const float2*)(Ab + i * MM + j);
            float2 rv2 = *(const float2*)(rn + j);
            float2 aj = *(const float2*)(adj + i * MM + j);
            float cg0 = fsig(val.x + wbv);
            float cg1 = fsig(val.y + wbv);
            float2 ov;
            ov.x = aj.x * cg0 + ax.x * rv2.x * (1.f - cg0);
            ov.y = aj.y * cg1 + ax.y * rv2.y * (1.f - cg1);
            *(float2*)(g_A + b * MM * MM + i * MM + j) = ov;
        }
    }
}

// ============================================================================
// Kernel 6: Z = r_l @ gc1_W
// ============================================================================
__global__ void __launch_bounds__(256) zk_kernel(const float* __restrict__ gc1_W)
{
    __shared__ float gw[30 * 128];
    __shared__ float rls[32 * 30];
    int tid = threadIdx.x, n0 = blockIdx.x * 32;
    for (int idx = tid; idx < 3840; idx += 256) gw[idx] = gc1_W[idx];
    for (int idx = tid; idx < 960; idx += 256) rls[idx] = g_rl[n0 * 30 + idx];
    __syncthreads();
    int h = tid & 127, sg = tid >> 7;
    float acc[16];
#pragma unroll
    for (int s = 0; s < 16; s++) acc[s] = 0.f;
    for (int q = 0; q < 30; q++) {
        float wv = gw[q * 128 + h];
#pragma unroll
        for (int s = 0; s < 16; s++)
            acc[s] += rls[(sg * 16 + s) * 30 + q] * wv;
    }
#pragma unroll
    for (int s = 0; s < 16; s++)
        g_Z[(n0 + sg * 16 + s) * HH + h] = acc[s];
}

// ============================================================================
// Kernel 7: h1 = relu(A @ Z + gc1_b)   fp32x2
// ============================================================================
__global__ void __launch_bounds__(256) h1_kernel(const float* __restrict__ gc1_b)
{
    __shared__ ull Asd[64 * 17];
    __shared__ float Bs[16 * 64];
    int b = blockIdx.z, i0 = blockIdx.y * 64, j0 = blockIdx.x * 64;
    const float* Ab = g_A + b * MM * MM;
    const float* Zb = g_Z + b * MM * HH;
    int tid = threadIdx.x;
    int ty = tid >> 4, tx = tid & 15;
    int lrow = tid >> 2, lkq = (tid & 3) * 4;
    ull acc[4][2];
#pragma unroll
    for (int r = 0; r < 4; r++) { acc[r][0] = 0ULL; acc[r][1] = 0ULL; }

    for (int kt = 0; kt < MM; kt += 16) {
        float4 av = *(const float4*)(Ab + (i0 + lrow) * MM + kt + lkq);
        Asd[lrow * 17 + lkq]     = fdup(av.x);
        Asd[lrow * 17 + lkq + 1] = fdup(av.y);
        Asd[lrow * 17 + lkq + 2] = fdup(av.z);
        Asd[lrow * 17 + lkq + 3] = fdup(av.w);
#pragma unroll
        for (int q = 0; q < 4; q++) {
            int idx = tid + q * 256;
            int r = idx >> 6, c = idx & 63;
            Bs[r * 64 + c] = Zb[(kt + r) * HH + j0 + c];
        }
        __syncthreads();
#pragma unroll
        for (int kk = 0; kk < 16; kk++) {
            ull b0 = *(const ull*)&Bs[kk * 64 + 2 * tx];
            ull b1 = *(const ull*)&Bs[kk * 64 + 32 + 2 * tx];
#pragma unroll
            for (int r = 0; r < 4; r++) {
                ull a = Asd[(ty + 16 * r) * 17 + kk];
                fma2(acc[r][0], a, b0);
                fma2(acc[r][1], a, b1);
            }
        }
        __syncthreads();
    }
#pragma unroll
    for (int r = 0; r < 4; r++) {
        int i = i0 + ty + 16 * r;
#pragma unroll
        for (int c2 = 0; c2 < 2; c2++) {
            int j = j0 + 2 * tx + 32 * c2;
            float2 val = fup(acc[r][c2]);
            g_h1[(b * MM + i) * HH + j]     = fmaxf(val.x + gc1_b[j], 0.f);
            g_h1[(b * MM + i) * HH + j + 1] = fmaxf(val.y + gc1_b[j + 1], 0.f);
        }
    }
}

// ============================================================================
// Kernel 8: Z2 = h1 @ gc2_W
// ============================================================================
__global__ void __launch_bounds__(320) z2_kernel(const float* __restrict__ gc2_W)
{
    __shared__ float g2[1280];
    __shared__ float h1s[32 * 128];
    int tid = threadIdx.x, n0 = blockIdx.x * 32;
    for (int idx = tid; idx < 1280; idx += 320) g2[idx] = gc2_W[idx];
    for (int idx = tid; idx < 4096; idx += 320) h1s[idx] = g_h1[n0 * HH + idx];
    __syncthreads();
    int s = tid / 10, k = tid % 10;
    float acc = 0.f;
#pragma unroll 8
    for (int j = 0; j < 128; j++)
        acc += h1s[s * 128 + j] * g2[j * 10 + k];
    g_Z2[(n0 + s) * KK + k] = acc;
}

// ============================================================================
// Kernel 9: out_spatial = relu(A @ Z2 + gc2_b)
// ============================================================================
__global__ void __launch_bounds__(320) spatial_kernel(const float* __restrict__ gc2_b)
{
    __shared__ float z2s[MM * KK];
    __shared__ float ats[32 * 33];
    int b = blockIdx.y, i0 = blockIdx.x * 32;
    int tid = threadIdx.x;
    for (int idx = tid; idx < MM * KK; idx += 320) z2s[idx] = g_Z2[b * MM * KK + idx];
    int il = tid / 10, k = tid % 10;
    float acc = 0.f;
    for (int j0 = 0; j0 < MM; j0 += 32) {
        __syncthreads();
        for (int idx = tid; idx < 1024; idx += 320) {
            int r = idx >> 5, c = idx & 31;
            ats[r * 33 + c] = g_A[b * MM * MM + (i0 + r) * MM + j0 + c];
        }
        __syncthreads();
#pragma unroll 8
        for (int c = 0; c < 32; c++)
            acc += ats[il * 33 + c] * z2s[(j0 + c) * KK + k];
    }
    g_sp[(b * MM + i0 + il) * KK + k] = fmaxf(acc + gc2_b[k], 0.f);
}

// ============================================================================
// Kernel 10: readout
// ============================================================================
__global__ void readout_kernel(const float* __restrict__ outW,
                               const float* __restrict__ outb,
                               float* __restrict__ outsig)
{
    __shared__ float ws[138];
    int tid = threadIdx.x;
    if (tid < 138) ws[tid] = outW[tid];
    __syncthreads();
    int n = blockIdx.x * 256 + tid;
    float acc = outb[0];
#pragma unroll
    for (int k = 0; k < 10; k++) acc += g_sp[n * KK + k] * ws[k];
#pragma unroll 4
    for (int h = 0; h < 128; h++) acc += g_hid[n * HH + h] * ws[10 + h];
    g_y[n] = acc;
    outsig[n] = fsig(acc);
}

// Kernel 11: loss
__global__ void loss_kernel(const float* __restrict__ Y, float* __restrict__ out0)
{
    __shared__ float red[256];
    int tid = threadIdx.x;
    float s = 0.f;
    for (int n = tid; n < BM; n += 256) {
        float v = g_y[n];
        s += fmaxf(v, 0.f) + log1pf(__expf(-fabsf(v))) - Y[n] * v;
    }
    red[tid] = s;
    __syncthreads();
    for (int st = 128; st > 0; st >>= 1) {
        if (tid < st) red[tid] += red[tid + st];
        __syncthreads();
    }
    if (tid == 0) out0[0] = red[0] / (float)BM;
}

// ============================================================================
extern "C" void kernel_launch(void* const* d_in, const int* in_sizes, int n_in,
                              void* d_out, int out_size)
{
    const float* X      = (const float*)d_in[0];
    const float* Y      = (const float*)d_in[1];
    const float* adj    = (const float*)d_in[2];
    const float* V      = (const float*)d_in[3];
    const float* bv     = (const float*)d_in[4];
    const float* W1     = (const float*)d_in[5];
    const float* b1     = (const float*)d_in[6];
    const float* W2     = (const float*)d_in[7];
    const float* Wb     = (const float*)d_in[8];
    const float* wb     = (const float*)d_in[9];
    const float* conv_w = (const float*)d_in[10];
    const float* conv_b = (const float*)d_in[11];
    const float* convl_w= (const float*)d_in[12];
    const float* convl_b= (const float*)d_in[13];
    const float* gWih   = (const float*)d_in[14];
    const float* gWhh   = (const float*)d_in[15];
    const float* gbih   = (const float*)d_in[16];
    const float* gbhh   = (const float*)d_in[17];
    const float* gc1_W  = (const float*)d_in[18];
    const float* gc1_b  = (const float*)d_in[19];
    const float* gc2_W  = (const float*)d_in[20];
    const float* gc2_b  = (const float*)d_in[21];
    const float* out_W  = (const float*)d_in[22];
    const float* out_b  = (const float*)d_in[23];
    float* out = (float*)d_out;

    const int gru_smem = (49152 + 128 * HS + 512) * 4;     // 217088
    const int p_smem   = (8192 + 8192 + 4096) * 4;          // 81920
    const int amx_smem = (4 * 64 * 66 + 64) * 4;            // 67840
    cudaFuncSetAttribute(gru_kernel, cudaFuncAttributeMaxDynamicSharedMemorySize, gru_smem);
    cudaFuncSetAttribute(p1p2_kernel, cudaFuncAttributeMaxDynamicSharedMemorySize, p_smem);
    cudaFuncSetAttribute(amx_kernel, cudaFuncAttributeMaxDynamicSharedMemorySize, amx_smem);

    wih_t_kernel<<<24, 256>>>(gWih, V);
    gru_kernel<<<128, 256, gru_smem>>>(X, gWhh, gbih, gbhh);
    conv_kernel<<<256, 160>>>(X, conv_w, conv_b, convl_w, convl_b);
    p1p2_kernel<<<128, 256, p_smem>>>(W1, W2, b1);
    amx_kernel<<<dim3(8, 8, 8), 256, amx_smem>>>(V, bv);
    rnrm_kernel<<<dim3(4, 8), 256>>>();
    gateA_kernel<<<dim3(8, 8, 8), 256>>>(Wb, adj, wb);
    zk_kernel<<<128, 256>>>(gc1_W);
    h1_kernel<<<dim3(2, 8, 8), 256>>>(gc1_b);
    z2_kernel<<<128, 320>>>(gc2_W);
    spatial_kernel<<<dim3(16, 8), 320>>>(gc2_b);
    readout_kernel<<<16, 256>>>(out_W, out_b, out + 1);
    loss_kernel<<<1, 256>>>(Y, out);
}

// round 4
// speedup vs baseline: 1.3730x; 1.1065x over previous
#include <cuda_runtime.h>
#include <cuda_bf16.h>

typedef unsigned long long ull;

#define BB 8
#define TT 20
#define MM 512
#define FF 16
#define HH 128
#define G3 384
#define BM 4096
#define HALF 64
#define KK 10

// ---------------- scratch ----------------
__device__ __align__(128) float g_hid[BM * HH];
__device__ __align__(128) float g_p1[BM * HALF];
__device__ __align__(128) float g_p2[BM * HALF];
__device__ __align__(128) float g_e1[BM * HALF];
__device__ __align__(128) float g_e2[BM * HALF];
__device__ __align__(128) float g_amx[BB * MM * MM];
__device__ __align__(128) float g_cs[BB * 8 * MM];   // per-(b,iblk,j) colsum partials
__device__ __align__(128) float g_rnrm[BM];
__device__ __align__(128) float g_A[BB * MM * MM];
__device__ __align__(128) float g_rl[BM * 30];
__device__ __align__(128) float g_Z[BM * HH];
__device__ __align__(128) float g_h1[BM * HH];
__device__ __align__(128) float g_Z2[BM * KK];
__device__ __align__(128) float g_sp[BM * KK];
__device__ __align__(128) float g_y[BM];
__device__ __align__(128) float g_wih4[FF * G3];
__device__ float g_sumV;

// ---------------- helpers ----------------
__device__ __forceinline__ float fsig(float x) {
    return __fdividef(1.f, 1.f + __expf(-x));
}
__device__ __forceinline__ float ftanh(float x) {
    x = fminf(15.f, fmaxf(-15.f, x));
    float t = __expf(2.f * x);
    return __fdividef(t - 1.f, t + 1.f);
}
__device__ __forceinline__ ull fdup(float x) {
    ull r; asm("mov.b64 %0, {%1, %1};" : "=l"(r) : "f"(x)); return r;
}
__device__ __forceinline__ float2 fup(ull v) {
    float2 r; asm("mov.b64 {%0, %1}, %2;" : "=f"(r.x), "=f"(r.y) : "l"(v)); return r;
}
__device__ __forceinline__ void fma2(ull& d, ull a, ull b) {
    asm("fma.rn.f32x2 %0, %1, %2, %0;" : "+l"(d) : "l"(a), "l"(b));
}
__device__ __forceinline__ ull add2(ull a, ull b) {
    ull r; asm("add.rn.f32x2 %0, %1, %2;" : "=l"(r) : "l"(a), "l"(b)); return r;
}
__device__ __forceinline__ ull mul2(ull a, ull b) {
    ull r; asm("mul.rn.f32x2 %0, %1, %2;" : "=l"(r) : "l"(a), "l"(b)); return r;
}

// ============================================================================
// Kernel 0: permute Wih; sumV
// ============================================================================
__global__ void wih_t_kernel(const float* __restrict__ Wih,
                             const float* __restrict__ V)
{
    int i = blockIdx.x * 256 + threadIdx.x;
    if (i < G3 * FF) {
        int f = i / G3, rem = i % G3;
        int wq = rem >> 7, r2 = rem & 127;
        int lane = r2 >> 2, e = r2 & 3;
        int g = wq * 128 + ((e >> 1) * 64) + 2 * lane + (e & 1);
        g_wih4[i] = Wih[g * FF + f];
    }
    if (i == 0) {
        float s = 0.f;
#pragma unroll
        for (int k = 0; k < HALF; k++) s += V[k];
        g_sumV = s;
    }
}

// ============================================================================
// Kernel 1: GRU (fp32x2, x prefetched into regs)
// ============================================================================
#define HS 36
__global__ void __launch_bounds__(256, 1) gru_kernel(
    const float* __restrict__ X, const float* __restrict__ Whh,
    const float* __restrict__ bih, const float* __restrict__ bhh)
{
    extern __shared__ float sm[];
    float* whh4 = sm;                 // 128*384
    float* hbuf = sm + 49152;         // 128*36
    float* xbuf = hbuf + 128 * HS;    // 512

    const int tid = threadIdx.x;
    const int lane = tid & 31;
    const int warp = tid >> 5;
    const int n0 = blockIdx.x * 32;
    const int b = n0 >> 9, m0 = n0 & 511;
    const int sb = warp * 4;
    const float* Xbase = X + ((size_t)b * TT * MM + m0) * FF;

    for (int idx = tid; idx < G3 * HH; idx += 256) {
        int k = idx / G3, rem = idx - k * G3;
        int wq = rem >> 7, r2 = rem & 127;
        int ln = r2 >> 2, e = r2 & 3;
        int g = wq * 128 + ((e >> 1) * 64) + 2 * ln + (e & 1);
        whh4[idx] = Whh[g * HH + k];
    }
    for (int idx = tid; idx < 128 * HS; idx += 256) hbuf[idx] = 0.f;

    ull br[2], bz[2], bnx[2], bnh[2];
#pragma unroll
    for (int p = 0; p < 2; p++) {
        int gg = 64 * p + 2 * lane;
        float2 t1 = *(const float2*)(bih + gg);
        float2 t2 = *(const float2*)(bhh + gg);
        br[p] = add2(*(const ull*)&t1, *(const ull*)&t2);
        t1 = *(const float2*)(bih + 128 + gg);
        t2 = *(const float2*)(bhh + 128 + gg);
        bz[p] = add2(*(const ull*)&t1, *(const ull*)&t2);
        t1 = *(const float2*)(bih + 256 + gg);
        bnx[p] = *(const ull*)&t1;
        t2 = *(const float2*)(bhh + 256 + gg);
        bnh[p] = *(const ull*)&t2;
    }

    float xr0 = Xbase[tid], xr1 = Xbase[256 + tid];

    for (int t = 0; t < TT; t++) {
        xbuf[tid] = xr0;               // wait: xbuf only 512; tid<256 stores 2
        xbuf[256 + tid] = xr1;
        __syncthreads();
        if (t + 1 < TT) {
            xr0 = Xbase[(t + 1) * MM * FF + tid];
            xr1 = Xbase[(t + 1) * MM * FF + 256 + tid];
        }

        ull ar[4][2], az[4][2], axn[4][2], ahn[4][2];
#pragma unroll
        for (int s = 0; s < 4; s++)
#pragma unroll
            for (int p = 0; p < 2; p++) {
                ar[s][p] = br[p]; az[s][p] = bz[p];
                axn[s][p] = bnx[p]; ahn[s][p] = bnh[p];
            }

#pragma unroll 4
        for (int f = 0; f < FF; f++) {
            const float* wf = g_wih4 + f * G3 + lane * 4;
            ulonglong2 w01 = *(const ulonglong2*)(wf);
            ulonglong2 w23 = *(const ulonglong2*)(wf + 128);
            ulonglong2 w45 = *(const ulonglong2*)(wf + 256);
            const float* xf = xbuf + sb * 16 + f;
#pragma unroll
            for (int s = 0; s < 4; s++) {
                ull xd = fdup(xf[s * 16]);
                fma2(ar[s][0], xd, w01.x);  fma2(ar[s][1], xd, w01.y);
                fma2(az[s][0], xd, w23.x);  fma2(az[s][1], xd, w23.y);
                fma2(axn[s][0], xd, w45.x); fma2(axn[s][1], xd, w45.y);
            }
        }
#pragma unroll 2
        for (int k = 0; k < HH; k++) {
            const float* wk = whh4 + k * G3 + lane * 4;
            ulonglong2 w01 = *(const ulonglong2*)(wk);
            ulonglong2 w23 = *(const ulonglong2*)(wk + 128);
            ulonglong2 w45 = *(const ulonglong2*)(wk + 256);
            float4 h4 = *(const float4*)(hbuf + k * HS + sb);
            ull hd0 = fdup(h4.x), hd1 = fdup(h4.y);
            ull hd2 = fdup(h4.z), hd3 = fdup(h4.w);
            fma2(ar[0][0], hd0, w01.x);  fma2(ar[0][1], hd0, w01.y);
            fma2(az[0][0], hd0, w23.x);  fma2(az[0][1], hd0, w23.y);
            fma2(ahn[0][0], hd0, w45.x); fma2(ahn[0][1], hd0, w45.y);
            fma2(ar[1][0], hd1, w01.x);  fma2(ar[1][1], hd1, w01.y);
            fma2(az[1][0], hd1, w23.x);  fma2(az[1][1], hd1, w23.y);
            fma2(ahn[1][0], hd1, w45.x); fma2(ahn[1][1], hd1, w45.y);
            fma2(ar[2][0], hd2, w01.x);  fma2(ar[2][1], hd2, w01.y);
            fma2(az[2][0], hd2, w23.x);  fma2(az[2][1], hd2, w23.y);
            fma2(ahn[2][0], hd2, w45.x); fma2(ahn[2][1], hd2, w45.y);
            fma2(ar[3][0], hd3, w01.x);  fma2(ar[3][1], hd3, w01.y);
            fma2(az[3][0], hd3, w23.x);  fma2(az[3][1], hd3, w23.y);
            fma2(ahn[3][0], hd3, w45.x); fma2(ahn[3][1], hd3, w45.y);
        }
        __syncthreads();
#pragma unroll
        for (int s = 0; s < 4; s++) {
            int col = sb + s;
#pragma unroll
            for (int p = 0; p < 2; p++) {
                int h0 = 64 * p + 2 * lane;
                float2 rv = fup(ar[s][p]);
                float2 zv = fup(az[s][p]);
                float2 xv = fup(axn[s][p]);
                float2 hv = fup(ahn[s][p]);
                float hold0 = hbuf[h0 * HS + col];
                float hold1 = hbuf[(h0 + 1) * HS + col];
                float r0 = fsig(rv.x), z0 = fsig(zv.x);
                float nn0 = ftanh(xv.x + r0 * hv.x);
                float r1 = fsig(rv.y), z1 = fsig(zv.y);
                float nn1 = ftanh(xv.y + r1 * hv.y);
                hbuf[h0 * HS + col]       = nn0 + z0 * (hold0 - nn0);
                hbuf[(h0 + 1) * HS + col] = nn1 + z1 * (hold1 - nn1);
            }
        }
    }
    __syncthreads();
    for (int idx = tid; idx < 32 * HH; idx += 256) {
        int s = idx >> 7, h = idx & 127;
        g_hid[(n0 + s) * HH + h] = hbuf[h * HS + s];
    }
}

// ============================================================================
// Kernel 2: p1/p2 + exps. 128 blocks x 256 thr; h-step-4 float4 ILP.
// ============================================================================
__global__ void __launch_bounds__(256) p1p2_kernel(
    const float* __restrict__ W1, const float* __restrict__ W2,
    const float* __restrict__ b1)
{
    extern __shared__ float smp[];
    float* w1t = smp;               // [h][65]
    float* w2t = w1t + 128 * 65;
    float* hs  = w2t + 128 * 65;    // [node][128]
    int tid = threadIdx.x;
    int n0 = blockIdx.x * 32;
    for (int idx = tid; idx < HALF * HH; idx += 256) {
        int k = idx >> 7, h = idx & 127;
        w1t[h * 65 + k] = W1[idx];
        w2t[h * 65 + k] = W2[idx];
    }
    for (int idx = tid; idx < 32 * HH; idx += 256) hs[idx] = g_hid[n0 * HH + idx];
    __syncthreads();
    int kk = tid & 63, grp = tid >> 6;
    float a1[8], a2[8];
    float bk = b1[kk];
#pragma unroll
    for (int s = 0; s < 8; s++) { a1[s] = bk; a2[s] = 0.f; }
    const float* hb = hs + grp * 8 * 128;
#pragma unroll 2
    for (int h = 0; h < 128; h += 4) {
        float wa0 = w1t[h * 65 + kk],       wa1 = w1t[(h + 1) * 65 + kk];
        float wa2 = w1t[(h + 2) * 65 + kk], wa3 = w1t[(h + 3) * 65 + kk];
        float wc0 = w2t[h * 65 + kk],       wc1 = w2t[(h + 1) * 65 + kk];
        float wc2 = w2t[(h + 2) * 65 + kk], wc3 = w2t[(h + 3) * 65 + kk];
#pragma unroll
        for (int s = 0; s < 8; s++) {
            float4 hv = *(const float4*)(hb + s * 128 + h);
            a1[s] += hv.x * wa0 + hv.y * wa1 + hv.z * wa2 + hv.w * wa3;
            a2[s] += hv.x * wc0 + hv.y * wc1 + hv.z * wc2 + hv.w * wc3;
        }
    }
#pragma unroll
    for (int s = 0; s < 8; s++) {
        int node = n0 + grp * 8 + s;
        float p1 = a1[s], p2 = a2[s];
        g_p1[node * 64 + kk] = p1;
        g_e1[node * 64 + kk] = __expf(fminf(p1, 60.f));
        g_p2[node * 64 + kk] = p2;
        g_e2[node * 64 + kk] = __expf(fminf(p2, 60.f));
    }
}

// ============================================================================
// Kernel 3: amx 64x64 tiles + fused per-tile column sum-of-squares partials
// ============================================================================
__global__ void __launch_bounds__(256) amx_kernel(
    const float* __restrict__ V, const float* __restrict__ bv)
{
    extern __shared__ float sma[];
    float* p1s = sma;               // [j][66]
    float* e1s = p1s + 64 * 66;
    float* p2s = e1s + 64 * 66;
    float* e2s = p2s + 64 * 66;
    float* Vs  = e2s + 64 * 66;
    int b = blockIdx.z, i0 = blockIdx.y * 64, j0 = blockIdx.x * 64;
    int tid = threadIdx.x;
    for (int idx = tid; idx < 64 * 64; idx += 256) {
        int r = idx >> 6, k = idx & 63;
        p1s[r * 66 + k] = g_p1[(b * MM + j0 + r) * HALF + k];
        e1s[r * 66 + k] = g_e1[(b * MM + j0 + r) * HALF + k];
        p2s[r * 66 + k] = g_p2[(b * MM + i0 + r) * HALF + k];
        e2s[r * 66 + k] = g_e2[(b * MM + i0 + r) * HALF + k];
    }
    if (tid < 64) Vs[tid] = V[tid];
    __syncthreads();
    int tyy = tid >> 4, txx = tid & 15;
    float accp[4][4], acce[4][4];
#pragma unroll
    for (int r = 0; r < 4; r++)
#pragma unroll
        for (int c = 0; c < 4; c++) { accp[r][c] = 0.f; acce[r][c] = 0.f; }

#pragma unroll 2
    for (int kp = 0; kp < 32; kp++) {
        int k = 2 * kp;
        float vk0 = Vs[k], vk1 = Vs[k + 1];
        ull p2r[4], e2r[4], p1c[4], e1c[4];
#pragma unroll
        for (int r = 0; r < 4; r++) {
            p2r[r] = *(const ull*)&p2s[(tyy + 16 * r) * 66 + k];
            e2r[r] = *(const ull*)&e2s[(tyy + 16 * r) * 66 + k];
        }
#pragma unroll
        for (int c = 0; c < 4; c++) {
            p1c[c] = *(const ull*)&p1s[(txx + 16 * c) * 66 + k];
            e1c[c] = *(const ull*)&e1s[(txx + 16 * c) * 66 + k];
        }
#pragma unroll
        for (int r = 0; r < 4; r++)
#pragma unroll
            for (int c = 0; c < 4; c++) {
                float2 v = fup(add2(p1c[c], p2r[r]));
                float2 m = fup(mul2(e1c[c], e2r[r]));
                accp[r][c] = fmaf(fmaxf(v.x, 0.f), vk0, accp[r][c]);
                accp[r][c] = fmaf(fmaxf(v.y, 0.f), vk1, accp[r][c]);
                acce[r][c] = fmaf(fminf(m.x, 1.f), vk0, acce[r][c]);
                acce[r][c] = fmaf(fminf(m.y, 1.f), vk1, acce[r][c]);
            }
    }
    float cst = bv[0] - g_sumV;
    float ps[4] = {0.f, 0.f, 0.f, 0.f};
#pragma unroll
    for (int r = 0; r < 4; r++) {
        int i = i0 + tyy + 16 * r;
#pragma unroll
        for (int c = 0; c < 4; c++) {
            int j = j0 + txx + 16 * c;
            float val = accp[r][c] + acce[r][c] + cst;
            g_amx[(b * MM + i) * MM + j] = val;
            ps[c] += val * val;
        }
    }
    // reduce per-column partials across the 16 tyy threads
    __syncthreads();
    float* scr = p1s;   // reuse: 64 cols x 16
#pragma unroll
    for (int c = 0; c < 4; c++)
        scr[(txx + 16 * c) * 16 + tyy] = ps[c];
    __syncthreads();
    if (tid < 64) {
        float s = 0.f;
#pragma unroll
        for (int q = 0; q < 16; q++) s += scr[tid * 16 + q];
        g_cs[(b * 8 + blockIdx.y) * MM + j0 + tid] = s;
    }
}

// Kernel 3b: combine 8 partials -> reciprocal norm
__global__ void rnrm_kernel()
{
    int idx = blockIdx.x * 512 + threadIdx.x;   // 4096
    int b = idx >> 9, j = idx & 511;
    float s = 0.f;
#pragma unroll
    for (int t = 0; t < 8; t++) s += g_cs[(b * 8 + t) * MM + j];
    g_rnrm[idx] = 1.f / fmaxf(sqrtf(s), 1e-12f);
}

// ============================================================================
// Kernel 4: conv branch
// ============================================================================
__global__ void __launch_bounds__(160) conv_kernel(
    const float* __restrict__ X, const float* __restrict__ cw,
    const float* __restrict__ cb, const float* __restrict__ clw,
    const float* __restrict__ clb)
{
    __shared__ float xs[16 * 320];
    __shared__ float cws[3200];
    __shared__ float clws[1600];
    int tid = threadIdx.x;
    int n0 = blockIdx.x * 16;
    int b = n0 >> 9, m0 = n0 & 511;
    for (int idx = tid; idx < 3200; idx += 160) cws[idx] = cw[idx];
    for (int idx = tid; idx < 1600; idx += 160) clws[idx] = clw[idx];
    for (int idx = tid; idx < 5120; idx += 160) {
        int w = idx >> 8, rem = idx & 255;
        int s = rem >> 4, f = rem & 15;
        xs[s * 320 + w * 16 + f] = X[((b * TT + w) * MM + m0) * FF + rem];
    }
    __syncthreads();
    int s = tid / 10, k = tid % 10;
    const float* xrow = xs + s * 320;
    const float* ck = cws + k * 320;
    float r = cb[k];
#pragma unroll
    for (int f = 0; f < 16; f++)
#pragma unroll
        for (int w = 0; w < 20; w++)
            r += xrow[w * 16 + f] * ck[f * 20 + w];
    const float* clk = clws + k * 160;
    float r0 = clb[k], r1 = clb[k];
#pragma unroll
    for (int f = 0; f < 16; f++)
#pragma unroll
        for (int j = 0; j < 10; j++) {
            float wv = clk[f * 10 + j];
            r0 += xrow[(2 * j) * 16 + f]     * wv;
            r1 += xrow[(2 * j + 1) * 16 + f] * wv;
        }
    int o = (n0 + s) * 30 + k * 3;
    g_rl[o]     = fmaxf(r, 0.f);
    g_rl[o + 1] = fmaxf(r0, 0.f);
    g_rl[o + 2] = fmaxf(r1, 0.f);
}

// ============================================================================
// Kernel 5: gateA 128x128 tile, row-pair packed fp32x2. grid (4,4,8) x 256.
// ============================================================================
__global__ void __launch_bounds__(256) gateA_kernel(
    const float* __restrict__ Wb, const float* __restrict__ adj,
    const float* __restrict__ wb)
{
    __shared__ float As[16 * 132];    // [k][row] rn-scaled
    __shared__ ull  bd[16 * 128];     // [k][col] dup
    int b = blockIdx.z, i0 = blockIdx.y * 128, j0 = blockIdx.x * 128;
    const float* Ab = g_amx + b * MM * MM;
    const float* rn = g_rnrm + b * MM;
    int tid = threadIdx.x;
    int ty = tid >> 4, tx = tid & 15;
    int lrow = tid >> 1, lkq = (tid & 1) * 8;
    ull acc[4][8];
#pragma unroll
    for (int r = 0; r < 4; r++)
#pragma unroll
        for (int c = 0; c < 8; c++) acc[r][c] = 0ULL;

    for (int kt = 0; kt < MM; kt += 16) {
        // A tile: 128 rows x 16 k, scaled by rn[k]
#pragma unroll
        for (int half = 0; half < 2; half++) {
            int kq = lkq + half * 4;
            float4 av = *(const float4*)(Ab + (i0 + lrow) * MM + kt + kq);
            float4 rv = *(const float4*)(rn + kt + kq);
            As[(kq + 0) * 132 + lrow] = av.x * rv.x;
            As[(kq + 1) * 132 + lrow] = av.y * rv.y;
            As[(kq + 2) * 132 + lrow] = av.z * rv.z;
            As[(kq + 3) * 132 + lrow] = av.w * rv.w;
        }
        // B tile dup: 16 k x 128 cols
#pragma unroll
        for (int q = 0; q < 8; q++) {
            int idx = tid + q * 256;
            int kk = idx >> 7, col = idx & 127;
            bd[kk * 128 + col] = fdup(Wb[(kt + kk) * MM + j0 + col]);
        }
        __syncthreads();
#pragma unroll
        for (int kk = 0; kk < 16; kk++) {
            ull a[4], bb[8];
#pragma unroll
            for (int r = 0; r < 4; r++)
                a[r] = *(const ull*)&As[kk * 132 + 2 * (ty + 16 * r)];
#pragma unroll
            for (int c = 0; c < 8; c++)
                bb[c] = bd[kk * 128 + tx + 16 * c];
#pragma unroll
            for (int r = 0; r < 4; r++)
#pragma unroll
                for (int c = 0; c < 8; c++)
                    fma2(acc[r][c], a[r], bb[c]);
        }
        __syncthreads();
    }
    float wbv = wb[0];
#pragma unroll
    for (int r = 0; r < 4; r++) {
        int ia = i0 + 2 * (ty + 16 * r);
#pragma unroll
        for (int c = 0; c < 8; c++) {
            int j = j0 + tx + 16 * c;
            float2 val = fup(acc[r][c]);
            float rj = rn[j];
            float aj0 = adj[ia * MM + j], aj1 = adj[(ia + 1) * MM + j];
            float ax0 = Ab[ia * MM + j] * rj, ax1 = Ab[(ia + 1) * MM + j] * rj;
            float cg0 = fsig(val.x + wbv);
            float cg1 = fsig(val.y + wbv);
            g_A[(b * MM + ia) * MM + j]     = aj0 * cg0 + ax0 * (1.f - cg0);
            g_A[(b * MM + ia + 1) * MM + j] = aj1 * cg1 + ax1 * (1.f - cg1);
        }
    }
}

// ============================================================================
// Kernel 6: Z = r_l @ gc1_W
// ============================================================================
__global__ void __launch_bounds__(256) zk_kernel(const float* __restrict__ gc1_W)
{
    __shared__ float gw[30 * 128];
    __shared__ float rls[32 * 30];
    int tid = threadIdx.x, n0 = blockIdx.x * 32;
    for (int idx = tid; idx < 3840; idx += 256) gw[idx] = gc1_W[idx];
    for (int idx = tid; idx < 960; idx += 256) rls[idx] = g_rl[n0 * 30 + idx];
    __syncthreads();
    int h = tid & 127, sg = tid >> 7;
    float acc[16];
#pragma unroll
    for (int s = 0; s < 16; s++) acc[s] = 0.f;
    for (int q = 0; q < 30; q++) {
        float wv = gw[q * 128 + h];
#pragma unroll
        for (int s = 0; s < 16; s++)
            acc[s] += rls[(sg * 16 + s) * 30 + q] * wv;
    }
#pragma unroll
    for (int s = 0; s < 16; s++)
        g_Z[(n0 + sg * 16 + s) * HH + h] = acc[s];
}

// ============================================================================
// Kernel 7: h1 = relu(A @ Z + gc1_b)
// ============================================================================
__global__ void __launch_bounds__(256) h1_kernel(const float* __restrict__ gc1_b)
{
    __shared__ ull Asd[64 * 17];
    __shared__ float Bs[16 * 64];
    int b = blockIdx.z, i0 = blockIdx.y * 64, j0 = blockIdx.x * 64;
    const float* Ab = g_A + b * MM * MM;
    const float* Zb = g_Z + b * MM * HH;
    int tid = threadIdx.x;
    int ty = tid >> 4, tx = tid & 15;
    int lrow = tid >> 2, lkq = (tid & 3) * 4;
    ull acc[4][2];
#pragma unroll
    for (int r = 0; r < 4; r++) { acc[r][0] = 0ULL; acc[r][1] = 0ULL; }

    for (int kt = 0; kt < MM; kt += 16) {
        float4 av = *(const float4*)(Ab + (i0 + lrow) * MM + kt + lkq);
        Asd[lrow * 17 + lkq]     = fdup(av.x);
        Asd[lrow * 17 + lkq + 1] = fdup(av.y);
        Asd[lrow * 17 + lkq + 2] = fdup(av.z);
        Asd[lrow * 17 + lkq + 3] = fdup(av.w);
#pragma unroll
        for (int q = 0; q < 4; q++) {
            int idx = tid + q * 256;
            int r = idx >> 6, c = idx & 63;
            Bs[r * 64 + c] = Zb[(kt + r) * HH + j0 + c];
        }
        __syncthreads();
#pragma unroll
        for (int kk = 0; kk < 16; kk++) {
            ull b0 = *(const ull*)&Bs[kk * 64 + 2 * tx];
            ull b1 = *(const ull*)&Bs[kk * 64 + 32 + 2 * tx];
#pragma unroll
            for (int r = 0; r < 4; r++) {
                ull a = Asd[(ty + 16 * r) * 17 + kk];
                fma2(acc[r][0], a, b0);
                fma2(acc[r][1], a, b1);
            }
        }
        __syncthreads();
    }
#pragma unroll
    for (int r = 0; r < 4; r++) {
        int i = i0 + ty + 16 * r;
#pragma unroll
        for (int c2 = 0; c2 < 2; c2++) {
            int j = j0 + 2 * tx + 32 * c2;
            float2 val = fup(acc[r][c2]);
            g_h1[(b * MM + i) * HH + j]     = fmaxf(val.x + gc1_b[j], 0.f);
            g_h1[(b * MM + i) * HH + j + 1] = fmaxf(val.y + gc1_b[j + 1], 0.f);
        }
    }
}

// ============================================================================
// Kernel 8: Z2 = h1 @ gc2_W
// ============================================================================
__global__ void __launch_bounds__(320) z2_kernel(const float* __restrict__ gc2_W)
{
    __shared__ float g2[1280];
    __shared__ float h1s[32 * 128];
    int tid = threadIdx.x, n0 = blockIdx.x * 32;
    for (int idx = tid; idx < 1280; idx += 320) g2[idx] = gc2_W[idx];
    for (int idx = tid; idx < 4096; idx += 320) h1s[idx] = g_h1[n0 * HH + idx];
    __syncthreads();
    int s = tid / 10, k = tid % 10;
    float acc = 0.f;
#pragma unroll 8
    for (int j = 0; j < 128; j++)
        acc += h1s[s * 128 + j] * g2[j * 10 + k];
    g_Z2[(n0 + s) * KK + k] = acc;
}

// ============================================================================
// Kernel 9: out_spatial = relu(A @ Z2 + gc2_b)
// ============================================================================
__global__ void __launch_bounds__(320) spatial_kernel(const float* __restrict__ gc2_b)
{
    __shared__ float z2s[MM * KK];
    __shared__ float ats[32 * 33];
    int b = blockIdx.y, i0 = blockIdx.x * 32;
    int tid = threadIdx.x;
    for (int idx = tid; idx < MM * KK; idx += 320) z2s[idx] = g_Z2[b * MM * KK + idx];
    int il = tid / 10, k = tid % 10;
    float acc = 0.f;
    for (int j0 = 0; j0 < MM; j0 += 32) {
        __syncthreads();
        for (int idx = tid; idx < 1024; idx += 320) {
            int r = idx >> 5, c = idx & 31;
            ats[r * 33 + c] = g_A[b * MM * MM + (i0 + r) * MM + j0 + c];
        }
        __syncthreads();
#pragma unroll 8
        for (int c = 0; c < 32; c++)
            acc += ats[il * 33 + c] * z2s[(j0 + c) * KK + k];
    }
    g_sp[(b * MM + i0 + il) * KK + k] = fmaxf(acc + gc2_b[k], 0.f);
}

// ============================================================================
// Kernel 10: readout
// ============================================================================
__global__ void readout_kernel(const float* __restrict__ outW,
                               const float* __restrict__ outb,
                               float* __restrict__ outsig)
{
    __shared__ float ws[138];
    int tid = threadIdx.x;
    if (tid < 138) ws[tid] = outW[tid];
    __syncthreads();
    int n = blockIdx.x * 256 + tid;
    float acc = outb[0];
#pragma unroll
    for (int k = 0; k < 10; k++) acc += g_sp[n * KK + k] * ws[k];
#pragma unroll 4
    for (int h = 0; h < 128; h++) acc += g_hid[n * HH + h] * ws[10 + h];
    g_y[n] = acc;
    outsig[n] = fsig(acc);
}

// Kernel 11: loss
__global__ void loss_kernel(const float* __restrict__ Y, float* __restrict__ out0)
{
    __shared__ float red[256];
    int tid = threadIdx.x;
    float s = 0.f;
    for (int n = tid; n < BM; n += 256) {
        float v = g_y[n];
        s += fmaxf(v, 0.f) + log1pf(__expf(-fabsf(v))) - Y[n] * v;
    }
    red[tid] = s;
    __syncthreads();
    for (int st = 128; st > 0; st >>= 1) {
        if (tid < st) red[tid] += red[tid + st];
        __syncthreads();
    }
    if (tid == 0) out0[0] = red[0] / (float)BM;
}

// ============================================================================
extern "C" void kernel_launch(void* const* d_in, const int* in_sizes, int n_in,
                              void* d_out, int out_size)
{
    const float* X      = (const float*)d_in[0];
    const float* Y      = (const float*)d_in[1];
    const float* adj    = (const float*)d_in[2];
    const float* V      = (const float*)d_in[3];
    const float* bv     = (const float*)d_in[4];
    const float* W1     = (const float*)d_in[5];
    const float* b1     = (const float*)d_in[6];
    const float* W2     = (const float*)d_in[7];
    const float* Wb     = (const float*)d_in[8];
    const float* wb     = (const float*)d_in[9];
    const float* conv_w = (const float*)d_in[10];
    const float* conv_b = (const float*)d_in[11];
    const float* convl_w= (const float*)d_in[12];
    const float* convl_b= (const float*)d_in[13];
    const float* gWih   = (const float*)d_in[14];
    const float* gWhh   = (const float*)d_in[15];
    const float* gbih   = (const float*)d_in[16];
    const float* gbhh   = (const float*)d_in[17];
    const float* gc1_W  = (const float*)d_in[18];
    const float* gc1_b  = (const float*)d_in[19];
    const float* gc2_W  = (const float*)d_in[20];
    const float* gc2_b  = (const float*)d_in[21];
    const float* out_W  = (const float*)d_in[22];
    const float* out_b  = (const float*)d_in[23];
    float* out = (float*)d_out;

    const int gru_smem = (49152 + 128 * HS + 512) * 4;
    const int p_smem   = (128 * 65 * 2 + 32 * 128) * 4;     // 49664 floats? -> bytes
    const int amx_smem = (4 * 64 * 66 + 64) * 4;
    cudaFuncSetAttribute(gru_kernel, cudaFuncAttributeMaxDynamicSharedMemorySize, gru_smem);
    cudaFuncSetAttribute(p1p2_kernel, cudaFuncAttributeMaxDynamicSharedMemorySize, p_smem);
    cudaFuncSetAttribute(amx_kernel, cudaFuncAttributeMaxDynamicSharedMemorySize, amx_smem);

    wih_t_kernel<<<24, 256>>>(gWih, V);
    gru_kernel<<<128, 256, gru_smem>>>(X, gWhh, gbih, gbhh);
    conv_kernel<<<256, 160>>>(X, conv_w, conv_b, convl_w, convl_b);
    p1p2_kernel<<<128, 256, p_smem>>>(W1, W2, b1);
    amx_kernel<<<dim3(8, 8, 8), 256, amx_smem>>>(V, bv);
    rnrm_kernel<<<8, 512>>>();
    gateA_kernel<<<dim3(4, 4, 8), 256>>>(Wb, adj, wb);
    zk_kernel<<<128, 256>>>(gc1_W);
    h1_kernel<<<dim3(2, 8, 8), 256>>>(gc1_b);
    z2_kernel<<<128, 320>>>(gc2_W);
    spatial_kernel<<<dim3(16, 8), 320>>>(gc2_b);
    readout_kernel<<<16, 256>>>(out_W, out_b, out + 1);
    loss_kernel<<<1, 256>>>(Y, out);
}